// round 2
// baseline (speedup 1.0000x reference)
#include <cuda_runtime.h>
#include <math.h>

#define HH   1024
#define NHH  16
#define HDD  64
#define BB   2
#define SS   2048
#define RR   (BB*SS)   // 4096 rows

// Scratch (no allocation allowed): 5 x 16 MB fp32 buffers.
__device__ float g_xn[RR*HH];
__device__ float g_q [RR*HH];   // [B*NH, S, HD]
__device__ float g_k [RR*HH];
__device__ float g_v [RR*HH];
__device__ float g_attn[RR*HH]; // [B, S, H]

// ---------------------------------------------------------------------------
// LayerNorm: one block per row, 256 threads, float4 per thread.
// ---------------------------------------------------------------------------
__global__ void ln_kernel(const float* __restrict__ x,
                          const float* __restrict__ gamma,
                          const float* __restrict__ beta) {
    int row = blockIdx.x;
    int t   = threadIdx.x;
    const float4* xr = (const float4*)(x + (size_t)row*HH);
    float4 v = xr[t];
    float s  = v.x + v.y + v.z + v.w;
    float sq = v.x*v.x + v.y*v.y + v.z*v.z + v.w*v.w;

    __shared__ float ssum[8], ssq[8];
    #pragma unroll
    for (int o = 16; o >= 1; o >>= 1) {
        s  += __shfl_xor_sync(0xffffffffu, s,  o);
        sq += __shfl_xor_sync(0xffffffffu, sq, o);
    }
    int warp = t >> 5, lane = t & 31;
    if (lane == 0) { ssum[warp] = s; ssq[warp] = sq; }
    __syncthreads();
    s = 0.f; sq = 0.f;
    #pragma unroll
    for (int i = 0; i < 8; i++) { s += ssum[i]; sq += ssq[i]; }

    float mu  = s * (1.0f/HH);
    float var = sq * (1.0f/HH) - mu*mu;
    float inv = rsqrtf(var + 1e-5f);

    float4 g  = ((const float4*)gamma)[t];
    float4 bt = ((const float4*)beta)[t];
    float4 o;
    o.x = (v.x-mu)*inv*g.x + bt.x;
    o.y = (v.y-mu)*inv*g.y + bt.y;
    o.z = (v.z-mu)*inv*g.z + bt.z;
    o.w = (v.w-mu)*inv*g.w + bt.w;
    ((float4*)(g_xn + (size_t)row*HH))[t] = o;
}

// ---------------------------------------------------------------------------
// NT-GEMM: C[i][j] = sum_k A[i][k] * W[j][k]
// 64x64 block tile, 16x16 threads, 4x4 per thread, BK=16.
// MODE 0/1/2: A=g_xn, dst = q/k/v in [B*NH, S, HD] layout.
// MODE 3:     A=g_attn, dst = out (plain [RR,H]) + bias + residual.
// ---------------------------------------------------------------------------
template<int MODE>
__global__ void gemm_nt(const float* __restrict__ W,
                        const float* __restrict__ bias,
                        const float* __restrict__ resid,
                        float* __restrict__ dstPlain) {
    __shared__ float As[64][17];
    __shared__ float Bs[64][17];

    const float* A = (MODE == 3) ? g_attn : g_xn;
    float* dst = (MODE == 0) ? g_q : (MODE == 1) ? g_k : (MODE == 2) ? g_v : dstPlain;

    int tx = threadIdx.x, ty = threadIdx.y;
    int tid = ty*16 + tx;
    int row0 = blockIdx.y * 64;
    int col0 = blockIdx.x * 64;

    float acc[4][4] = {};

    for (int kt = 0; kt < HH; kt += 16) {
        #pragma unroll
        for (int t = 0; t < 4; t++) {
            int idx = tid + t*256;
            int r = idx >> 4, c = idx & 15;
            As[r][c] = A[(size_t)(row0 + r)*HH + kt + c];
            Bs[r][c] = W[(size_t)(col0 + r)*HH + kt + c];
        }
        __syncthreads();
        #pragma unroll
        for (int k = 0; k < 16; k++) {
            float a[4], b[4];
            #pragma unroll
            for (int i = 0; i < 4; i++) a[i] = As[ty*4 + i][k];
            #pragma unroll
            for (int j = 0; j < 4; j++) b[j] = Bs[tx*4 + j][k];
            #pragma unroll
            for (int i = 0; i < 4; i++)
                #pragma unroll
                for (int j = 0; j < 4; j++)
                    acc[i][j] += a[i] * b[j];
        }
        __syncthreads();
    }

    #pragma unroll
    for (int i = 0; i < 4; i++) {
        int gi = row0 + ty*4 + i;
        #pragma unroll
        for (int j = 0; j < 4; j++) {
            int gj = col0 + tx*4 + j;
            if (MODE < 3) {
                int b  = gi >> 11;        // row / 2048
                int s_ = gi & 2047;
                int h  = gj >> 6;         // col / 64
                int d  = gj & 63;
                dst[(size_t)(((b << 4) + h)*SS + s_)*HDD + d] = acc[i][j];
            } else {
                dst[(size_t)gi*HH + gj] = acc[i][j] + bias[gj] + resid[(size_t)gi*HH + gj];
            }
        }
    }
}

// ---------------------------------------------------------------------------
// Flash attention: one block per (b*NH + h, 64-query tile).
// smem: Qs[64][64] (pre-scaled), KPs[64][65] (K tile, reused for P tile),
//       Vs[64][64]. 16x16 threads, 4x4 scores / 4x4 output per thread.
// ---------------------------------------------------------------------------
__global__ void attn_kernel() {
    extern __shared__ float sm[];
    float* Qs  = sm;                 // 64*64
    float* KPs = sm + 64*64;         // 64*65
    float* Vs  = KPs + 64*65;        // 64*64

    int tx = threadIdx.x, ty = threadIdx.y;
    int tid = ty*16 + tx;
    int bh = blockIdx.y;             // 0..31
    int qt = blockIdx.x;             // 0..31

    const float* Qp = g_q + (size_t)bh*SS*HDD + (size_t)qt*64*HDD;
    const float* Kp = g_k + (size_t)bh*SS*HDD;
    const float* Vp = g_v + (size_t)bh*SS*HDD;
    const float scale = 0.125f;      // 1/sqrt(64)

    #pragma unroll
    for (int t = 0; t < 16; t++) {
        int idx = tid + t*256;       // 4096 elems, [r][c] = linear
        Qs[idx] = Qp[idx] * scale;
    }

    float m[4], l[4], O[4][4];
    #pragma unroll
    for (int i = 0; i < 4; i++) {
        m[i] = -1e30f; l[i] = 0.f;
        #pragma unroll
        for (int j = 0; j < 4; j++) O[i][j] = 0.f;
    }

    for (int kt = 0; kt < SS/64; kt++) {
        __syncthreads();  // prior PV reads done (and Qs visible on iter 0)
        #pragma unroll
        for (int t = 0; t < 16; t++) {
            int idx = tid + t*256;
            int r = idx >> 6, c = idx & 63;
            KPs[r*65 + c] = Kp[(size_t)kt*64*HDD + idx];
            Vs[idx]       = Vp[(size_t)kt*64*HDD + idx];
        }
        __syncthreads();

        // S = (Q*scale) @ K^T
        float s[4][4] = {};
        #pragma unroll
        for (int k = 0; k < 64; k++) {
            float a[4], b[4];
            #pragma unroll
            for (int i = 0; i < 4; i++) a[i] = Qs[(ty*4 + i)*64 + k];
            #pragma unroll
            for (int j = 0; j < 4; j++) b[j] = KPs[(tx*4 + j)*65 + k];
            #pragma unroll
            for (int i = 0; i < 4; i++)
                #pragma unroll
                for (int j = 0; j < 4; j++)
                    s[i][j] += a[i]*b[j];
        }
        __syncthreads();  // done reading KPs as K; about to overwrite with P

        // Online softmax per query row (row owned by 16 lanes, width-16 shuffles)
        #pragma unroll
        for (int i = 0; i < 4; i++) {
            float tm = fmaxf(fmaxf(s[i][0], s[i][1]), fmaxf(s[i][2], s[i][3]));
            #pragma unroll
            for (int o = 8; o >= 1; o >>= 1)
                tm = fmaxf(tm, __shfl_xor_sync(0xffffffffu, tm, o, 16));
            float mn   = fmaxf(m[i], tm);
            float corr = __expf(m[i] - mn);
            float rs = 0.f;
            #pragma unroll
            for (int j = 0; j < 4; j++) {
                float p = __expf(s[i][j] - mn);
                KPs[(ty*4 + i)*65 + tx*4 + j] = p;
                rs += p;
            }
            #pragma unroll
            for (int o = 8; o >= 1; o >>= 1)
                rs += __shfl_xor_sync(0xffffffffu, rs, o, 16);
            l[i] = l[i]*corr + rs;
            m[i] = mn;
            #pragma unroll
            for (int j = 0; j < 4; j++) O[i][j] *= corr;
        }
        __syncthreads();  // P visible

        // O += P @ V
        #pragma unroll
        for (int k = 0; k < 64; k++) {
            float a[4];
            #pragma unroll
            for (int i = 0; i < 4; i++) a[i] = KPs[(ty*4 + i)*65 + k];
            float4 b4 = *(const float4*)&Vs[k*64 + tx*4];
            #pragma unroll
            for (int i = 0; i < 4; i++) {
                O[i][0] += a[i]*b4.x;
                O[i][1] += a[i]*b4.y;
                O[i][2] += a[i]*b4.z;
                O[i][3] += a[i]*b4.w;
            }
        }
    }

    // Normalize and store to [B, S, H]
    int b = bh >> 4, h = bh & 15;
    #pragma unroll
    for (int i = 0; i < 4; i++) {
        float inv = 1.0f / l[i];
        int gi = b*SS + qt*64 + ty*4 + i;
        int colbase = h*64 + tx*4;
        #pragma unroll
        for (int j = 0; j < 4; j++)
            g_attn[(size_t)gi*HH + colbase + j] = O[i][j] * inv;
    }
}

// ---------------------------------------------------------------------------
extern "C" void kernel_launch(void* const* d_in, const int* in_sizes, int n_in,
                              void* d_out, int out_size) {
    const float* x     = (const float*)d_in[0];
    const float* Wq    = (const float*)d_in[1];
    const float* Wk    = (const float*)d_in[2];
    const float* Wv    = (const float*)d_in[3];
    const float* Wo    = (const float*)d_in[4];
    const float* bo    = (const float*)d_in[5];
    const float* gamma = (const float*)d_in[6];
    const float* beta  = (const float*)d_in[7];
    float* out = (float*)d_out;

    ln_kernel<<<RR, 256>>>(x, gamma, beta);

    dim3 thr(16, 16);
    dim3 grid(HH/64, RR/64);   // (16, 64)
    gemm_nt<0><<<grid, thr>>>(Wq, nullptr, nullptr, nullptr);
    gemm_nt<1><<<grid, thr>>>(Wk, nullptr, nullptr, nullptr);
    gemm_nt<2><<<grid, thr>>>(Wv, nullptr, nullptr, nullptr);

    size_t smem = (size_t)(64*64 + 64*65 + 64*64) * sizeof(float);  // 49408 B
    cudaFuncSetAttribute(attn_kernel, cudaFuncAttributeMaxDynamicSharedMemorySize, (int)smem);
    attn_kernel<<<dim3(SS/64, BB*NHH), thr, smem>>>();

    gemm_nt<3><<<grid, thr>>>(Wo, bo, x, out);
}

// round 5
// speedup vs baseline: 1.8208x; 1.8208x over previous
#include <cuda_runtime.h>
#include <cuda_bf16.h>
#include <cstdint>
#include <math.h>

#define HH   1024
#define NHH  16
#define HDD  64
#define BB   2
#define SS   2048
#define RR   (BB*SS)   // 4096 rows

// ---------------- device scratch (no allocations allowed) -------------------
__device__ float g_q[RR*HH];            // [B*NH, S, HD] fp32
__device__ float g_k[RR*HH];
__device__ float g_v[RR*HH];
__device__ __nv_bfloat16 g_xn_hi[RR*HH], g_xn_lo[RR*HH];     // LN output split
__device__ __nv_bfloat16 g_w_hi[4*HH*HH], g_w_lo[4*HH*HH];   // Wq,Wk,Wv,Wo split
__device__ __nv_bfloat16 g_at_hi[RR*HH], g_at_lo[RR*HH];     // attention out split

// ---------------- helpers ---------------------------------------------------
__device__ __forceinline__ uint32_t smem_u32(const void* p) {
    uint32_t a;
    asm("{ .reg .u64 t; cvta.to.shared.u64 t, %1; cvt.u32.u64 %0, t; }" : "=r"(a) : "l"(p));
    return a;
}
#define SWZ(o) ((o) ^ (((o) >> 3) & 0x70))

__device__ __forceinline__ void ldsm4(uint32_t& r0, uint32_t& r1, uint32_t& r2, uint32_t& r3,
                                      uint32_t a) {
    asm volatile("ldmatrix.sync.aligned.m8n8.x4.shared.b16 {%0,%1,%2,%3}, [%4];"
                 : "=r"(r0), "=r"(r1), "=r"(r2), "=r"(r3) : "r"(a));
}
__device__ __forceinline__ void mma16816(float* c, const uint32_t* a, const uint32_t* b) {
    asm volatile("mma.sync.aligned.m16n8k16.row.col.f32.bf16.bf16.f32 "
                 "{%0,%1,%2,%3}, {%4,%5,%6,%7}, {%8,%9}, {%0,%1,%2,%3};"
                 : "+f"(c[0]), "+f"(c[1]), "+f"(c[2]), "+f"(c[3])
                 : "r"(a[0]), "r"(a[1]), "r"(a[2]), "r"(a[3]), "r"(b[0]), "r"(b[1]));
}

// ---------------------------------------------------------------------------
// LayerNorm: one block per row, 256 threads, float4 per thread; emits bf16 hi/lo.
// ---------------------------------------------------------------------------
__global__ void ln_kernel(const float* __restrict__ x,
                          const float* __restrict__ gamma,
                          const float* __restrict__ beta) {
    int row = blockIdx.x;
    int t   = threadIdx.x;
    const float4* xr = (const float4*)(x + (size_t)row*HH);
    float4 v = xr[t];
    float s  = v.x + v.y + v.z + v.w;
    float sq = v.x*v.x + v.y*v.y + v.z*v.z + v.w*v.w;

    __shared__ float ssum[8], ssq[8];
    #pragma unroll
    for (int o = 16; o >= 1; o >>= 1) {
        s  += __shfl_xor_sync(0xffffffffu, s,  o);
        sq += __shfl_xor_sync(0xffffffffu, sq, o);
    }
    int warp = t >> 5, lane = t & 31;
    if (lane == 0) { ssum[warp] = s; ssq[warp] = sq; }
    __syncthreads();
    s = 0.f; sq = 0.f;
    #pragma unroll
    for (int i = 0; i < 8; i++) { s += ssum[i]; sq += ssq[i]; }

    float mu  = s * (1.0f/HH);
    float var = sq * (1.0f/HH) - mu*mu;
    float inv = rsqrtf(var + 1e-5f);

    float4 g  = ((const float4*)gamma)[t];
    float4 bt = ((const float4*)beta)[t];
    float o[4];
    o[0] = (v.x-mu)*inv*g.x + bt.x;
    o[1] = (v.y-mu)*inv*g.y + bt.y;
    o[2] = (v.z-mu)*inv*g.z + bt.z;
    o[3] = (v.w-mu)*inv*g.w + bt.w;

    size_t base = (size_t)row*HH + t*4;
    #pragma unroll
    for (int i = 0; i < 4; i++) {
        __nv_bfloat16 h = __float2bfloat16(o[i]);
        g_xn_hi[base+i] = h;
        g_xn_lo[base+i] = __float2bfloat16(o[i] - __bfloat162float(h));
    }
}

// ---------------------------------------------------------------------------
// Weight conversion fp32 -> bf16 hi/lo, all 4 W at once (4M elems).
// ---------------------------------------------------------------------------
__global__ void convw_kernel(const float* __restrict__ Wq, const float* __restrict__ Wk,
                             const float* __restrict__ Wv, const float* __restrict__ Wo) {
    int i = blockIdx.x*blockDim.x + threadIdx.x;
    const int M = HH*HH;
    const float* src = (i < M) ? Wq : (i < 2*M) ? Wk : (i < 3*M) ? Wv : Wo;
    float x = src[i & (M-1)];
    __nv_bfloat16 h = __float2bfloat16(x);
    g_w_hi[i] = h;
    g_w_lo[i] = __float2bfloat16(x - __bfloat162float(h));
}

// ---------------------------------------------------------------------------
// Split-bf16 HMMA NT-GEMM: C[i][j] = sum_k A[i][k] * W[j][k]  (~fp32 precise)
// 128x128 block tile, 8 warps (2m x 4n of 64x32), K-chunk 64, double buffer.
// Smem stage (64 KB): Ahi | Alo | Bhi | Blo, each 128 rows x 64 bf16, SW128.
// MODE 0: A = xn (hi/lo), W = {Wq,Wk,Wv}[blockIdx.z], dst = q/k/v head-split.
// MODE 3: A = attn (hi/lo), W = Wo, dst = out + bias + residual.
// ---------------------------------------------------------------------------
template<int MODE>
__global__ __launch_bounds__(256, 1) void gemm_mma(const float* __restrict__ bo,
                                                   const float* __restrict__ resid,
                                                   float* __restrict__ out) {
    extern __shared__ char sm[];
    uint32_t smb = smem_u32(sm);

    int tid = threadIdx.x;
    int w = tid >> 5, lane = tid & 31;
    int wm = w & 1, wn = w >> 1;                  // warp tile: (wm*64, wn*32)
    int row0 = blockIdx.y * 128;
    int col0 = blockIdx.x * 128;
    int widx = (MODE == 3) ? 3 : blockIdx.z;

    const __nv_bfloat16* Ahi = (MODE == 3) ? g_at_hi : g_xn_hi;
    const __nv_bfloat16* Alo = (MODE == 3) ? g_at_lo : g_xn_lo;
    const __nv_bfloat16* Bhi = g_w_hi + (size_t)widx*HH*HH;
    const __nv_bfloat16* Blo = g_w_lo + (size_t)widx*HH*HH;

    float acc[4][4][4];
    #pragma unroll
    for (int i = 0; i < 4; i++)
        #pragma unroll
        for (int j = 0; j < 4; j++)
            #pragma unroll
            for (int q = 0; q < 4; q++) acc[i][j][q] = 0.f;

    auto load_chunk = [&](int chunk) {
        int kt = chunk * 64;
        char* stg = sm + (size_t)(chunk & 1) * 65536u;
        #pragma unroll
        for (int t = 0; t < 16; t++) {
            int idx = tid + t*256;                // 0..4095 uint4 slots
            int a   = idx >> 10;                  // tile: 0=Ahi 1=Alo 2=Bhi 3=Blo
            int e   = idx & 1023;
            int r   = e >> 3, c16 = e & 7;
            const __nv_bfloat16* src =
                (a == 0) ? Ahi + (size_t)(row0 + r)*HH + kt :
                (a == 1) ? Alo + (size_t)(row0 + r)*HH + kt :
                (a == 2) ? Bhi + (size_t)(col0 + r)*HH + kt :
                           Blo + (size_t)(col0 + r)*HH + kt;
            uint4 v = ((const uint4*)src)[c16];
            uint32_t o = (uint32_t)(r*128 + c16*16);
            *(uint4*)(stg + (size_t)a*16384u + SWZ(o)) = v;
        }
    };

    load_chunk(0);
    __syncthreads();

    // ldmatrix lane->address components (constant across k16)
    int a_r  = wm*64 + ((lane >> 3) & 1)*8 + (lane & 7);   // + mf*16
    int a_ks = (lane >> 4);                                 // + k16*2
    int b_r  = wn*32 + ((lane >> 4) & 1)*8 + (lane & 7);    // + nh*16
    int b_ks = ((lane >> 3) & 1);                           // + k16*2

    for (int chunk = 0; chunk < 16; ++chunk) {
        if (chunk + 1 < 16) load_chunk(chunk + 1);
        uint32_t st = smb + (uint32_t)(chunk & 1) * 65536u;

        #pragma unroll
        for (int k16 = 0; k16 < 4; ++k16) {
            int ksA = (a_ks + k16*2) * 16;
            int ksB = (b_ks + k16*2) * 16;

            uint32_t Af[4][4], Al[4][4], Bf[4][2], Bl[4][2];
            #pragma unroll
            for (int mf = 0; mf < 4; mf++) {
                uint32_t off = SWZ((uint32_t)((a_r + mf*16)*128 + ksA));
                ldsm4(Af[mf][0], Af[mf][1], Af[mf][2], Af[mf][3], st + off);
                ldsm4(Al[mf][0], Al[mf][1], Al[mf][2], Al[mf][3], st + 16384u + off);
            }
            #pragma unroll
            for (int nh = 0; nh < 2; nh++) {
                uint32_t off = SWZ((uint32_t)((b_r + nh*16)*128 + ksB));
                uint32_t r0, r1, r2, r3;
                ldsm4(r0, r1, r2, r3, st + 32768u + off);
                Bf[nh*2+0][0] = r0; Bf[nh*2+0][1] = r1;
                Bf[nh*2+1][0] = r2; Bf[nh*2+1][1] = r3;
                ldsm4(r0, r1, r2, r3, st + 49152u + off);
                Bl[nh*2+0][0] = r0; Bl[nh*2+0][1] = r1;
                Bl[nh*2+1][0] = r2; Bl[nh*2+1][1] = r3;
            }
            #pragma unroll
            for (int mf = 0; mf < 4; mf++)
                #pragma unroll
                for (int nf = 0; nf < 4; nf++) {
                    mma16816(acc[mf][nf], Af[mf], Bf[nf]);   // hi*hi
                    mma16816(acc[mf][nf], Af[mf], Bl[nf]);   // hi*lo
                    mma16816(acc[mf][nf], Al[mf], Bf[nf]);   // lo*hi
                }
        }
        __syncthreads();
    }

    // epilogue: thread owns rows (mr, mr+8), cols (nc, nc+1) per (mf, nf)
    #pragma unroll
    for (int mf = 0; mf < 4; mf++) {
        int mr = row0 + wm*64 + mf*16 + (lane >> 2);
        #pragma unroll
        for (int nf = 0; nf < 4; nf++) {
            int nc = col0 + wn*32 + nf*8 + (lane & 3)*2;
            #pragma unroll
            for (int half = 0; half < 2; half++) {
                int gi = mr + half*8;
                float v0 = acc[mf][nf][half*2 + 0];
                float v1 = acc[mf][nf][half*2 + 1];
                if (MODE < 3) {
                    int b  = gi >> 11;
                    int s_ = gi & 2047;
                    int h  = nc >> 6;
                    int d  = nc & 63;
                    float* dst = (blockIdx.z == 0) ? g_q : (blockIdx.z == 1) ? g_k : g_v;
                    float2* p = (float2*)&dst[(size_t)(((b << 4) + h)*SS + s_)*HDD + d];
                    *p = make_float2(v0, v1);
                } else {
                    size_t base = (size_t)gi*HH + nc;
                    const float2 rr = *(const float2*)&resid[base];
                    float2* p = (float2*)&out[base];
                    *p = make_float2(v0 + bo[nc] + rr.x, v1 + bo[nc+1] + rr.y);
                }
            }
        }
    }
}

// ---------------------------------------------------------------------------
// Flash attention (FFMA path); epilogue emits bf16 hi/lo for the O-projection.
// ---------------------------------------------------------------------------
__global__ void attn_kernel() {
    extern __shared__ float smf[];
    float* Qs  = smf;                // 64*64
    float* KPs = smf + 64*64;        // 64*65
    float* Vs  = KPs + 64*65;        // 64*64

    int tx = threadIdx.x, ty = threadIdx.y;
    int tid = ty*16 + tx;
    int bh = blockIdx.y;
    int qt = blockIdx.x;

    const float* Qp = g_q + (size_t)bh*SS*HDD + (size_t)qt*64*HDD;
    const float* Kp = g_k + (size_t)bh*SS*HDD;
    const float* Vp = g_v + (size_t)bh*SS*HDD;
    const float scale = 0.125f;

    #pragma unroll
    for (int t = 0; t < 16; t++) {
        int idx = tid + t*256;
        Qs[idx] = Qp[idx] * scale;
    }

    float m[4], l[4], O[4][4];
    #pragma unroll
    for (int i = 0; i < 4; i++) {
        m[i] = -1e30f; l[i] = 0.f;
        #pragma unroll
        for (int j = 0; j < 4; j++) O[i][j] = 0.f;
    }

    for (int kt = 0; kt < SS/64; kt++) {
        __syncthreads();
        #pragma unroll
        for (int t = 0; t < 16; t++) {
            int idx = tid + t*256;
            int r = idx >> 6, c = idx & 63;
            KPs[r*65 + c] = Kp[(size_t)kt*64*HDD + idx];
            Vs[idx]       = Vp[(size_t)kt*64*HDD + idx];
        }
        __syncthreads();

        float s[4][4] = {};
        #pragma unroll
        for (int k = 0; k < 64; k++) {
            float a[4], b[4];
            #pragma unroll
            for (int i = 0; i < 4; i++) a[i] = Qs[(ty*4 + i)*64 + k];
            #pragma unroll
            for (int j = 0; j < 4; j++) b[j] = KPs[(tx*4 + j)*65 + k];
            #pragma unroll
            for (int i = 0; i < 4; i++)
                #pragma unroll
                for (int j = 0; j < 4; j++)
                    s[i][j] += a[i]*b[j];
        }
        __syncthreads();

        #pragma unroll
        for (int i = 0; i < 4; i++) {
            float tm = fmaxf(fmaxf(s[i][0], s[i][1]), fmaxf(s[i][2], s[i][3]));
            #pragma unroll
            for (int o = 8; o >= 1; o >>= 1)
                tm = fmaxf(tm, __shfl_xor_sync(0xffffffffu, tm, o, 16));
            float mn   = fmaxf(m[i], tm);
            float corr = __expf(m[i] - mn);
            float rs = 0.f;
            #pragma unroll
            for (int j = 0; j < 4; j++) {
                float p = __expf(s[i][j] - mn);
                KPs[(ty*4 + i)*65 + tx*4 + j] = p;
                rs += p;
            }
            #pragma unroll
            for (int o = 8; o >= 1; o >>= 1)
                rs += __shfl_xor_sync(0xffffffffu, rs, o, 16);
            l[i] = l[i]*corr + rs;
            m[i] = mn;
            #pragma unroll
            for (int j = 0; j < 4; j++) O[i][j] *= corr;
        }
        __syncthreads();

        #pragma unroll
        for (int k = 0; k < 64; k++) {
            float a[4];
            #pragma unroll
            for (int i = 0; i < 4; i++) a[i] = KPs[(ty*4 + i)*65 + k];
            float4 b4 = *(const float4*)&Vs[k*64 + tx*4];
            #pragma unroll
            for (int i = 0; i < 4; i++) {
                O[i][0] += a[i]*b4.x;
                O[i][1] += a[i]*b4.y;
                O[i][2] += a[i]*b4.z;
                O[i][3] += a[i]*b4.w;
            }
        }
    }

    int b = bh >> 4, h = bh & 15;
    #pragma unroll
    for (int i = 0; i < 4; i++) {
        float inv = 1.0f / l[i];
        int gi = b*SS + qt*64 + ty*4 + i;
        int colbase = h*64 + tx*4;
        #pragma unroll
        for (int j = 0; j < 4; j++) {
            float val = O[i][j] * inv;
            size_t idx = (size_t)gi*HH + colbase + j;
            __nv_bfloat16 hh = __float2bfloat16(val);
            g_at_hi[idx] = hh;
            g_at_lo[idx] = __float2bfloat16(val - __bfloat162float(hh));
        }
    }
}

// ---------------------------------------------------------------------------
extern "C" void kernel_launch(void* const* d_in, const int* in_sizes, int n_in,
                              void* d_out, int out_size) {
    const float* x     = (const float*)d_in[0];
    const float* Wq    = (const float*)d_in[1];
    const float* Wk    = (const float*)d_in[2];
    const float* Wv    = (const float*)d_in[3];
    const float* Wo    = (const float*)d_in[4];
    const float* bo    = (const float*)d_in[5];
    const float* gamma = (const float*)d_in[6];
    const float* beta  = (const float*)d_in[7];
    float* out = (float*)d_out;

    ln_kernel<<<RR, 256>>>(x, gamma, beta);
    convw_kernel<<<(4*HH*HH)/256, 256>>>(Wq, Wk, Wv, Wo);

    const int GSMEM = 2*65536;   // two 64 KB stages
    cudaFuncSetAttribute(gemm_mma<0>, cudaFuncAttributeMaxDynamicSharedMemorySize, GSMEM);
    cudaFuncSetAttribute(gemm_mma<3>, cudaFuncAttributeMaxDynamicSharedMemorySize, GSMEM);

    gemm_mma<0><<<dim3(HH/128, RR/128, 3), 256, GSMEM>>>(nullptr, nullptr, nullptr);

    size_t asmem = (size_t)(64*64 + 64*65 + 64*64) * sizeof(float);
    cudaFuncSetAttribute(attn_kernel, cudaFuncAttributeMaxDynamicSharedMemorySize, (int)asmem);
    attn_kernel<<<dim3(SS/64, BB*NHH), dim3(16,16), asmem>>>();

    gemm_mma<3><<<dim3(HH/128, RR/128, 1), 256, GSMEM>>>(bo, x, out);
}

// round 7
// speedup vs baseline: 2.9547x; 1.6228x over previous
#include <cuda_runtime.h>
#include <cuda_bf16.h>
#include <cstdint>
#include <math.h>

#define HH   1024
#define NHH  16
#define HDD  64
#define BB   2
#define SS   2048
#define RR   (BB*SS)   // 4096 rows

// ---------------- device scratch (no allocations allowed) -------------------
__device__ __nv_bfloat16 g_qhi[RR*HH], g_qlo[RR*HH];   // [B*NH, S, HD], pre-scaled 0.125
__device__ __nv_bfloat16 g_khi[RR*HH], g_klo[RR*HH];
__device__ __nv_bfloat16 g_vhi[RR*HH], g_vlo[RR*HH];
__device__ __nv_bfloat16 g_xn_hi[RR*HH], g_xn_lo[RR*HH];     // LN output split
__device__ __nv_bfloat16 g_w_hi[4*HH*HH], g_w_lo[4*HH*HH];   // Wq,Wk,Wv,Wo split
__device__ __nv_bfloat16 g_at_hi[RR*HH], g_at_lo[RR*HH];     // attention out split

// ---------------- helpers ---------------------------------------------------
__device__ __forceinline__ uint32_t smem_u32(const void* p) {
    uint32_t a;
    asm("{ .reg .u64 t; cvta.to.shared.u64 t, %1; cvt.u32.u64 %0, t; }" : "=r"(a) : "l"(p));
    return a;
}
#define SWZ(o) ((o) ^ (((o) >> 3) & 0x70))

__device__ __forceinline__ void ldsm4(uint32_t& r0, uint32_t& r1, uint32_t& r2, uint32_t& r3,
                                      uint32_t a) {
    asm volatile("ldmatrix.sync.aligned.m8n8.x4.shared.b16 {%0,%1,%2,%3}, [%4];"
                 : "=r"(r0), "=r"(r1), "=r"(r2), "=r"(r3) : "r"(a));
}
__device__ __forceinline__ void ldsm4t(uint32_t& r0, uint32_t& r1, uint32_t& r2, uint32_t& r3,
                                       uint32_t a) {
    asm volatile("ldmatrix.sync.aligned.m8n8.x4.trans.shared.b16 {%0,%1,%2,%3}, [%4];"
                 : "=r"(r0), "=r"(r1), "=r"(r2), "=r"(r3) : "r"(a));
}
__device__ __forceinline__ void mma16816(float* c, const uint32_t* a, const uint32_t* b) {
    asm volatile("mma.sync.aligned.m16n8k16.row.col.f32.bf16.bf16.f32 "
                 "{%0,%1,%2,%3}, {%4,%5,%6,%7}, {%8,%9}, {%0,%1,%2,%3};"
                 : "+f"(c[0]), "+f"(c[1]), "+f"(c[2]), "+f"(c[3])
                 : "r"(a[0]), "r"(a[1]), "r"(a[2]), "r"(a[3]), "r"(b[0]), "r"(b[1]));
}
// pack two fp32 -> bf16x2 (lo half = first element)
__device__ __forceinline__ uint32_t packbf(float p0, float p1) {
    uint32_t r;
    asm("cvt.rn.bf16x2.f32 %0, %1, %2;" : "=r"(r) : "f"(p1), "f"(p0));
    return r;
}
__device__ __forceinline__ float bfh(float x) {   // hi part as float
    return __bfloat162float(__float2bfloat16(x));
}

// ---------------------------------------------------------------------------
// LayerNorm: one block per row, 256 threads, float4 per thread; emits bf16 hi/lo.
// ---------------------------------------------------------------------------
__global__ void ln_kernel(const float* __restrict__ x,
                          const float* __restrict__ gamma,
                          const float* __restrict__ beta) {
    int row = blockIdx.x;
    int t   = threadIdx.x;
    const float4* xr = (const float4*)(x + (size_t)row*HH);
    float4 v = xr[t];
    float s  = v.x + v.y + v.z + v.w;
    float sq = v.x*v.x + v.y*v.y + v.z*v.z + v.w*v.w;

    __shared__ float ssum[8], ssq[8];
    #pragma unroll
    for (int o = 16; o >= 1; o >>= 1) {
        s  += __shfl_xor_sync(0xffffffffu, s,  o);
        sq += __shfl_xor_sync(0xffffffffu, sq, o);
    }
    int warp = t >> 5, lane = t & 31;
    if (lane == 0) { ssum[warp] = s; ssq[warp] = sq; }
    __syncthreads();
    s = 0.f; sq = 0.f;
    #pragma unroll
    for (int i = 0; i < 8; i++) { s += ssum[i]; sq += ssq[i]; }

    float mu  = s * (1.0f/HH);
    float var = sq * (1.0f/HH) - mu*mu;
    float inv = rsqrtf(var + 1e-5f);

    float4 g  = ((const float4*)gamma)[t];
    float4 bt = ((const float4*)beta)[t];
    float o[4];
    o[0] = (v.x-mu)*inv*g.x + bt.x;
    o[1] = (v.y-mu)*inv*g.y + bt.y;
    o[2] = (v.z-mu)*inv*g.z + bt.z;
    o[3] = (v.w-mu)*inv*g.w + bt.w;

    size_t base = (size_t)row*HH + t*4;
    #pragma unroll
    for (int i = 0; i < 4; i++) {
        __nv_bfloat16 h = __float2bfloat16(o[i]);
        g_xn_hi[base+i] = h;
        g_xn_lo[base+i] = __float2bfloat16(o[i] - __bfloat162float(h));
    }
}

// ---------------------------------------------------------------------------
// Weight conversion fp32 -> bf16 hi/lo, all 4 W at once.
// ---------------------------------------------------------------------------
__global__ void convw_kernel(const float* __restrict__ Wq, const float* __restrict__ Wk,
                             const float* __restrict__ Wv, const float* __restrict__ Wo) {
    int i = blockIdx.x*blockDim.x + threadIdx.x;
    const int M = HH*HH;
    const float* src = (i < M) ? Wq : (i < 2*M) ? Wk : (i < 3*M) ? Wv : Wo;
    float x = src[i & (M-1)];
    __nv_bfloat16 h = __float2bfloat16(x);
    g_w_hi[i] = h;
    g_w_lo[i] = __float2bfloat16(x - __bfloat162float(h));
}

// ---------------------------------------------------------------------------
// Split-bf16 HMMA NT-GEMM (as R4). MODE 0: dst = q/k/v split bf16 head-layout
// (q pre-scaled 0.125). MODE 3: dst = out + bias + residual (fp32).
// ---------------------------------------------------------------------------
template<int MODE>
__global__ __launch_bounds__(256, 1) void gemm_mma(const float* __restrict__ bo,
                                                   const float* __restrict__ resid,
                                                   float* __restrict__ out) {
    extern __shared__ char sm[];
    uint32_t smb = smem_u32(sm);

    int tid = threadIdx.x;
    int w = tid >> 5, lane = tid & 31;
    int wm = w & 1, wn = w >> 1;
    int row0 = blockIdx.y * 128;
    int col0 = blockIdx.x * 128;
    int widx = (MODE == 3) ? 3 : blockIdx.z;

    const __nv_bfloat16* Ahi = (MODE == 3) ? g_at_hi : g_xn_hi;
    const __nv_bfloat16* Alo = (MODE == 3) ? g_at_lo : g_xn_lo;
    const __nv_bfloat16* Bhi = g_w_hi + (size_t)widx*HH*HH;
    const __nv_bfloat16* Blo = g_w_lo + (size_t)widx*HH*HH;

    float acc[4][4][4];
    #pragma unroll
    for (int i = 0; i < 4; i++)
        #pragma unroll
        for (int j = 0; j < 4; j++)
            #pragma unroll
            for (int q = 0; q < 4; q++) acc[i][j][q] = 0.f;

    auto load_chunk = [&](int chunk) {
        int kt = chunk * 64;
        char* stg = sm + (size_t)(chunk & 1) * 65536u;
        #pragma unroll
        for (int t = 0; t < 16; t++) {
            int idx = tid + t*256;
            int a   = idx >> 10;
            int e   = idx & 1023;
            int r   = e >> 3, c16 = e & 7;
            const __nv_bfloat16* src =
                (a == 0) ? Ahi + (size_t)(row0 + r)*HH + kt :
                (a == 1) ? Alo + (size_t)(row0 + r)*HH + kt :
                (a == 2) ? Bhi + (size_t)(col0 + r)*HH + kt :
                           Blo + (size_t)(col0 + r)*HH + kt;
            uint4 v = ((const uint4*)src)[c16];
            uint32_t o = (uint32_t)(r*128 + c16*16);
            *(uint4*)(stg + (size_t)a*16384u + SWZ(o)) = v;
        }
    };

    load_chunk(0);
    __syncthreads();

    int a_r  = wm*64 + ((lane >> 3) & 1)*8 + (lane & 7);
    int a_ks = (lane >> 4);
    int b_r  = wn*32 + ((lane >> 4) & 1)*8 + (lane & 7);
    int b_ks = ((lane >> 3) & 1);

    for (int chunk = 0; chunk < 16; ++chunk) {
        if (chunk + 1 < 16) load_chunk(chunk + 1);
        uint32_t st = smb + (uint32_t)(chunk & 1) * 65536u;

        #pragma unroll
        for (int k16 = 0; k16 < 4; ++k16) {
            int ksA = (a_ks + k16*2) * 16;
            int ksB = (b_ks + k16*2) * 16;

            uint32_t Af[4][4], Al[4][4], Bf[4][2], Bl[4][2];
            #pragma unroll
            for (int mf = 0; mf < 4; mf++) {
                uint32_t off = SWZ((uint32_t)((a_r + mf*16)*128 + ksA));
                ldsm4(Af[mf][0], Af[mf][1], Af[mf][2], Af[mf][3], st + off);
                ldsm4(Al[mf][0], Al[mf][1], Al[mf][2], Al[mf][3], st + 16384u + off);
            }
            #pragma unroll
            for (int nh = 0; nh < 2; nh++) {
                uint32_t off = SWZ((uint32_t)((b_r + nh*16)*128 + ksB));
                uint32_t r0, r1, r2, r3;
                ldsm4(r0, r1, r2, r3, st + 32768u + off);
                Bf[nh*2+0][0] = r0; Bf[nh*2+0][1] = r1;
                Bf[nh*2+1][0] = r2; Bf[nh*2+1][1] = r3;
                ldsm4(r0, r1, r2, r3, st + 49152u + off);
                Bl[nh*2+0][0] = r0; Bl[nh*2+0][1] = r1;
                Bl[nh*2+1][0] = r2; Bl[nh*2+1][1] = r3;
            }
            #pragma unroll
            for (int mf = 0; mf < 4; mf++)
                #pragma unroll
                for (int nf = 0; nf < 4; nf++) {
                    mma16816(acc[mf][nf], Af[mf], Bf[nf]);
                    mma16816(acc[mf][nf], Af[mf], Bl[nf]);
                    mma16816(acc[mf][nf], Al[mf], Bf[nf]);
                }
        }
        __syncthreads();
    }

    float qscale = (MODE < 3 && blockIdx.z == 0) ? 0.125f : 1.0f;
    #pragma unroll
    for (int mf = 0; mf < 4; mf++) {
        int mr = row0 + wm*64 + mf*16 + (lane >> 2);
        #pragma unroll
        for (int nf = 0; nf < 4; nf++) {
            int nc = col0 + wn*32 + nf*8 + (lane & 3)*2;
            #pragma unroll
            for (int half = 0; half < 2; half++) {
                int gi = mr + half*8;
                float v0 = acc[mf][nf][half*2 + 0];
                float v1 = acc[mf][nf][half*2 + 1];
                if (MODE < 3) {
                    v0 *= qscale; v1 *= qscale;
                    int b  = gi >> 11;
                    int s_ = gi & 2047;
                    int h  = nc >> 6;
                    int d  = nc & 63;
                    __nv_bfloat16* dhi = (blockIdx.z == 0) ? g_qhi : (blockIdx.z == 1) ? g_khi : g_vhi;
                    __nv_bfloat16* dlo = (blockIdx.z == 0) ? g_qlo : (blockIdx.z == 1) ? g_klo : g_vlo;
                    size_t base = (size_t)(((b << 4) + h)*SS + s_)*HDD + d;
                    __nv_bfloat16 h0 = __float2bfloat16(v0);
                    __nv_bfloat16 h1 = __float2bfloat16(v1);
                    *(__nv_bfloat162*)&dhi[base] = __halves2bfloat162(h0, h1);
                    *(__nv_bfloat162*)&dlo[base] = __halves2bfloat162(
                        __float2bfloat16(v0 - __bfloat162float(h0)),
                        __float2bfloat16(v1 - __bfloat162float(h1)));
                } else {
                    size_t base = (size_t)gi*HH + nc;
                    const float2 rr = *(const float2*)&resid[base];
                    float2* p = (float2*)&out[base];
                    *p = make_float2(v0 + bo[nc] + rr.x, v1 + bo[nc+1] + rr.y);
                }
            }
        }
    }
}

// ---------------------------------------------------------------------------
// HMMA flash attention: block = (bh, 64-query tile), 4 warps x 16 q-rows.
// K-tiles of 64 keys/iter. Full split-bf16 (3-term) for QK^T and PV.
// Smem 32KB: [Khi|Klo|Vhi|Vlo] 8KB each; Q staged in first 16KB before loop.
// ---------------------------------------------------------------------------
__global__ __launch_bounds__(128) void attn_mma() {
    extern __shared__ char sm[];
    uint32_t smb = smem_u32(sm);

    int tid = threadIdx.x;
    int w = tid >> 5, lane = tid & 31;
    int bh = blockIdx.y;
    int qt = blockIdx.x;
    size_t bhoff = (size_t)bh*SS*HDD;

    // ---- stage Q tile (64x64 hi/lo) and preload A-fragments ----
    {
        const __nv_bfloat16* Qh = g_qhi + bhoff + (size_t)qt*64*HDD;
        const __nv_bfloat16* Ql = g_qlo + bhoff + (size_t)qt*64*HDD;
        #pragma unroll
        for (int t = 0; t < 8; t++) {
            int idx = tid + t*128;            // 0..1023 uint4 slots
            int a   = idx >> 9;               // 0=hi,1=lo
            int e   = idx & 511;
            int r   = e >> 3, c16 = e & 7;
            const __nv_bfloat16* src = (a ? Ql : Qh) + (size_t)r*HDD;
            uint4 v = ((const uint4*)src)[c16];
            *(uint4*)(sm + (size_t)a*8192u + SWZ((uint32_t)(r*128 + c16*16))) = v;
        }
    }
    __syncthreads();

    uint32_t qh[4][4], ql[4][4];
    {
        int a_r  = w*16 + ((lane >> 3) & 1)*8 + (lane & 7);
        int a_ks = (lane >> 4);
        #pragma unroll
        for (int k16 = 0; k16 < 4; k16++) {
            uint32_t off = SWZ((uint32_t)(a_r*128 + (a_ks + k16*2)*16));
            ldsm4(qh[k16][0], qh[k16][1], qh[k16][2], qh[k16][3], smb + off);
            ldsm4(ql[k16][0], ql[k16][1], ql[k16][2], ql[k16][3], smb + 8192u + off);
        }
    }

    float m0 = -1e30f, m1 = -1e30f, l0 = 0.f, l1 = 0.f;
    float O[8][4];
    #pragma unroll
    for (int n = 0; n < 8; n++)
        #pragma unroll
        for (int q = 0; q < 4; q++) O[n][q] = 0.f;

    const __nv_bfloat16* Kh = g_khi + bhoff;
    const __nv_bfloat16* Kl = g_klo + bhoff;
    const __nv_bfloat16* Vh = g_vhi + bhoff;
    const __nv_bfloat16* Vl = g_vlo + bhoff;

    int kb_row = ((lane >> 4) & 1)*8 + (lane & 7);
    int kb_k   = ((lane >> 3) & 1);
    int v_row  = ((lane >> 3) & 1)*8 + (lane & 7);
    int v_col  = ((lane >> 4) & 1)*8;

    for (int kt = 0; kt < SS/64; kt++) {
        __syncthreads();    // prior reads done (incl. Q frag loads on iter 0)
        #pragma unroll
        for (int t = 0; t < 16; t++) {
            int idx = tid + t*128;            // 0..2047 uint4 slots
            int a   = idx >> 9;               // 0=Khi 1=Klo 2=Vhi 3=Vlo
            int e   = idx & 511;
            int r   = e >> 3, c16 = e & 7;
            const __nv_bfloat16* src =
                ((a == 0) ? Kh : (a == 1) ? Kl : (a == 2) ? Vh : Vl)
                + (size_t)(kt*64 + r)*HDD;
            uint4 v = ((const uint4*)src)[c16];
            *(uint4*)(sm + (size_t)a*8192u + SWZ((uint32_t)(r*128 + c16*16))) = v;
        }
        __syncthreads();

        // ---- S = Q K^T (3-term split) ----
        float s[8][4];
        #pragma unroll
        for (int n = 0; n < 8; n++)
            #pragma unroll
            for (int q = 0; q < 4; q++) s[n][q] = 0.f;

        #pragma unroll
        for (int k16 = 0; k16 < 4; k16++) {
            uint32_t Bh_[8][2], Bl_[8][2];
            #pragma unroll
            for (int np = 0; np < 4; np++) {
                uint32_t off = SWZ((uint32_t)((np*16 + kb_row)*128 + (kb_k + k16*2)*16));
                uint32_t r0, r1, r2, r3;
                ldsm4(r0, r1, r2, r3, smb + off);
                Bh_[np*2+0][0] = r0; Bh_[np*2+0][1] = r1;
                Bh_[np*2+1][0] = r2; Bh_[np*2+1][1] = r3;
                ldsm4(r0, r1, r2, r3, smb + 8192u + off);
                Bl_[np*2+0][0] = r0; Bl_[np*2+0][1] = r1;
                Bl_[np*2+1][0] = r2; Bl_[np*2+1][1] = r3;
            }
            #pragma unroll
            for (int n = 0; n < 8; n++) {
                mma16816(s[n], qh[k16], Bh_[n]);
                mma16816(s[n], qh[k16], Bl_[n]);
                mma16816(s[n], ql[k16], Bh_[n]);
            }
        }

        // ---- online softmax (rows g=lane>>2 and g+8; quad shuffles) ----
        float mx0 = -1e30f, mx1 = -1e30f;
        #pragma unroll
        for (int n = 0; n < 8; n++) {
            mx0 = fmaxf(mx0, fmaxf(s[n][0], s[n][1]));
            mx1 = fmaxf(mx1, fmaxf(s[n][2], s[n][3]));
        }
        mx0 = fmaxf(mx0, __shfl_xor_sync(0xffffffffu, mx0, 1, 4));
        mx0 = fmaxf(mx0, __shfl_xor_sync(0xffffffffu, mx0, 2, 4));
        mx1 = fmaxf(mx1, __shfl_xor_sync(0xffffffffu, mx1, 1, 4));
        mx1 = fmaxf(mx1, __shfl_xor_sync(0xffffffffu, mx1, 2, 4));
        float m0n = fmaxf(m0, mx0), m1n = fmaxf(m1, mx1);
        float c0 = __expf(m0 - m0n), c1 = __expf(m1 - m1n);
        m0 = m0n; m1 = m1n;

        float rs0 = 0.f, rs1 = 0.f;
        #pragma unroll
        for (int n = 0; n < 8; n++) {
            s[n][0] = __expf(s[n][0] - m0); rs0 += s[n][0];
            s[n][1] = __expf(s[n][1] - m0); rs0 += s[n][1];
            s[n][2] = __expf(s[n][2] - m1); rs1 += s[n][2];
            s[n][3] = __expf(s[n][3] - m1); rs1 += s[n][3];
        }
        rs0 += __shfl_xor_sync(0xffffffffu, rs0, 1, 4);
        rs0 += __shfl_xor_sync(0xffffffffu, rs0, 2, 4);
        rs1 += __shfl_xor_sync(0xffffffffu, rs1, 1, 4);
        rs1 += __shfl_xor_sync(0xffffffffu, rs1, 2, 4);
        l0 = l0*c0 + rs0;
        l1 = l1*c1 + rs1;
        #pragma unroll
        for (int n = 0; n < 8; n++) {
            O[n][0] *= c0; O[n][1] *= c0; O[n][2] *= c1; O[n][3] *= c1;
        }

        // ---- O += P V (3-term split; P from s via C->A fragment identity) ----
        #pragma unroll
        for (int k16 = 0; k16 < 4; k16++) {
            // P hi/lo A-fragments for keys 16*k16..+15
            float p00 = s[2*k16][0],   p01 = s[2*k16][1];
            float p02 = s[2*k16][2],   p03 = s[2*k16][3];
            float p10 = s[2*k16+1][0], p11 = s[2*k16+1][1];
            float p12 = s[2*k16+1][2], p13 = s[2*k16+1][3];
            float h00 = bfh(p00), h01 = bfh(p01), h02 = bfh(p02), h03 = bfh(p03);
            float h10 = bfh(p10), h11 = bfh(p11), h12 = bfh(p12), h13 = bfh(p13);
            uint32_t ph[4], pl[4];
            ph[0] = packbf(h00, h01);           ph[1] = packbf(h02, h03);
            ph[2] = packbf(h10, h11);           ph[3] = packbf(h12, h13);
            pl[0] = packbf(p00-h00, p01-h01);   pl[1] = packbf(p02-h02, p03-h03);
            pl[2] = packbf(p10-h10, p11-h11);   pl[3] = packbf(p12-h12, p13-h13);

            uint32_t vh[8][2], vl[8][2];
            #pragma unroll
            for (int np = 0; np < 4; np++) {
                uint32_t off = SWZ((uint32_t)((k16*16 + v_row)*128 + (np*16 + v_col)*2));
                uint32_t r0, r1, r2, r3;
                ldsm4t(r0, r1, r2, r3, smb + 16384u + off);
                vh[np*2+0][0] = r0; vh[np*2+0][1] = r1;
                vh[np*2+1][0] = r2; vh[np*2+1][1] = r3;
                ldsm4t(r0, r1, r2, r3, smb + 24576u + off);
                vl[np*2+0][0] = r0; vl[np*2+0][1] = r1;
                vl[np*2+1][0] = r2; vl[np*2+1][1] = r3;
            }
            #pragma unroll
            for (int n = 0; n < 8; n++) {
                mma16816(O[n], ph, vh[n]);
                mma16816(O[n], ph, vl[n]);
                mma16816(O[n], pl, vh[n]);
            }
        }
    }

    // ---- epilogue: O/l -> g_at hi/lo, [B,S,H] with head offset ----
    int b = bh >> 4, h = bh & 15;
    float inv0 = 1.0f / l0, inv1 = 1.0f / l1;
    int gi0 = b*SS + qt*64 + w*16 + (lane >> 2);
    int col = h*64 + (lane & 3)*2;
    #pragma unroll
    for (int n = 0; n < 8; n++) {
        #pragma unroll
        for (int half = 0; half < 2; half++) {
            int gi = gi0 + half*8;
            float v0 = O[n][half*2+0] * (half ? inv1 : inv0);
            float v1 = O[n][half*2+1] * (half ? inv1 : inv0);
            size_t idx = (size_t)gi*HH + col + n*8;
            __nv_bfloat16 h0 = __float2bfloat16(v0);
            __nv_bfloat16 h1 = __float2bfloat16(v1);
            *(__nv_bfloat162*)&g_at_hi[idx] = __halves2bfloat162(h0, h1);
            *(__nv_bfloat162*)&g_at_lo[idx] = __halves2bfloat162(
                __float2bfloat16(v0 - __bfloat162float(h0)),
                __float2bfloat16(v1 - __bfloat162float(h1)));
        }
    }
}

// ---------------------------------------------------------------------------
extern "C" void kernel_launch(void* const* d_in, const int* in_sizes, int n_in,
                              void* d_out, int out_size) {
    const float* x     = (const float*)d_in[0];
    const float* Wq    = (const float*)d_in[1];
    const float* Wk    = (const float*)d_in[2];
    const float* Wv    = (const float*)d_in[3];
    const float* Wo    = (const float*)d_in[4];
    const float* bo    = (const float*)d_in[5];
    const float* gamma = (const float*)d_in[6];
    const float* beta  = (const float*)d_in[7];
    float* out = (float*)d_out;

    ln_kernel<<<RR, 256>>>(x, gamma, beta);
    convw_kernel<<<(4*HH*HH)/256, 256>>>(Wq, Wk, Wv, Wo);

    const int GSMEM = 2*65536;
    cudaFuncSetAttribute(gemm_mma<0>, cudaFuncAttributeMaxDynamicSharedMemorySize, GSMEM);
    cudaFuncSetAttribute(gemm_mma<3>, cudaFuncAttributeMaxDynamicSharedMemorySize, GSMEM);

    gemm_mma<0><<<dim3(HH/128, RR/128, 3), 256, GSMEM>>>(nullptr, nullptr, nullptr);

    const int ASMEM = 32768;
    cudaFuncSetAttribute(attn_mma, cudaFuncAttributeMaxDynamicSharedMemorySize, ASMEM);
    attn_mma<<<dim3(SS/64, BB*NHH), 128, ASMEM>>>();

    gemm_mma<3><<<dim3(HH/128, RR/128, 1), 256, GSMEM>>>(bo, x, out);
}

// round 8
// speedup vs baseline: 3.6675x; 1.2412x over previous
#include <cuda_runtime.h>
#include <cuda_bf16.h>
#include <cstdint>
#include <math.h>

#define HH   1024
#define NHH  16
#define HDD  64
#define BB   2
#define SS   2048
#define RR   (BB*SS)   // 4096 rows

// ---------------- device scratch (no allocations allowed) -------------------
__device__ __nv_bfloat16 g_qhi[RR*HH], g_qlo[RR*HH];   // [B*NH, S, HD], pre-scaled 0.125
__device__ __nv_bfloat16 g_khi[RR*HH], g_klo[RR*HH];
__device__ __nv_bfloat16 g_vhi[RR*HH], g_vlo[RR*HH];
__device__ __nv_bfloat16 g_xn_hi[RR*HH], g_xn_lo[RR*HH];     // LN output split
__device__ __nv_bfloat16 g_w_hi[4*HH*HH], g_w_lo[4*HH*HH];   // Wq,Wk,Wv,Wo split
__device__ __nv_bfloat16 g_at_hi[RR*HH], g_at_lo[RR*HH];     // attention out split

// ---------------- helpers ---------------------------------------------------
__device__ __forceinline__ uint32_t smem_u32(const void* p) {
    uint32_t a;
    asm("{ .reg .u64 t; cvta.to.shared.u64 t, %1; cvt.u32.u64 %0, t; }" : "=r"(a) : "l"(p));
    return a;
}
#define SWZ(o) ((o) ^ (((o) >> 3) & 0x70))

__device__ __forceinline__ void cpasync16(uint32_t dst, const void* src) {
    asm volatile("cp.async.cg.shared.global [%0], [%1], 16;" :: "r"(dst), "l"(src));
}
#define CP_COMMIT() asm volatile("cp.async.commit_group;" ::: "memory")
#define CP_WAIT(n)  asm volatile("cp.async.wait_group %0;" :: "n"(n) : "memory")

__device__ __forceinline__ void ldsm4(uint32_t& r0, uint32_t& r1, uint32_t& r2, uint32_t& r3,
                                      uint32_t a) {
    asm volatile("ldmatrix.sync.aligned.m8n8.x4.shared.b16 {%0,%1,%2,%3}, [%4];"
                 : "=r"(r0), "=r"(r1), "=r"(r2), "=r"(r3) : "r"(a));
}
__device__ __forceinline__ void ldsm4t(uint32_t& r0, uint32_t& r1, uint32_t& r2, uint32_t& r3,
                                       uint32_t a) {
    asm volatile("ldmatrix.sync.aligned.m8n8.x4.trans.shared.b16 {%0,%1,%2,%3}, [%4];"
                 : "=r"(r0), "=r"(r1), "=r"(r2), "=r"(r3) : "r"(a));
}
__device__ __forceinline__ void mma16816(float* c, const uint32_t* a, const uint32_t* b) {
    asm volatile("mma.sync.aligned.m16n8k16.row.col.f32.bf16.bf16.f32 "
                 "{%0,%1,%2,%3}, {%4,%5,%6,%7}, {%8,%9}, {%0,%1,%2,%3};"
                 : "+f"(c[0]), "+f"(c[1]), "+f"(c[2]), "+f"(c[3])
                 : "r"(a[0]), "r"(a[1]), "r"(a[2]), "r"(a[3]), "r"(b[0]), "r"(b[1]));
}
__device__ __forceinline__ uint32_t packbf(float p0, float p1) {
    uint32_t r;
    asm("cvt.rn.bf16x2.f32 %0, %1, %2;" : "=r"(r) : "f"(p1), "f"(p0));
    return r;
}
__device__ __forceinline__ float bfh(float x) {
    return __bfloat162float(__float2bfloat16(x));
}

// ---------------------------------------------------------------------------
// LayerNorm: one block per row, 256 threads, float4 per thread; emits bf16 hi/lo.
// ---------------------------------------------------------------------------
__global__ void ln_kernel(const float* __restrict__ x,
                          const float* __restrict__ gamma,
                          const float* __restrict__ beta) {
    int row = blockIdx.x;
    int t   = threadIdx.x;
    const float4* xr = (const float4*)(x + (size_t)row*HH);
    float4 v = xr[t];
    float s  = v.x + v.y + v.z + v.w;
    float sq = v.x*v.x + v.y*v.y + v.z*v.z + v.w*v.w;

    __shared__ float ssum[8], ssq[8];
    #pragma unroll
    for (int o = 16; o >= 1; o >>= 1) {
        s  += __shfl_xor_sync(0xffffffffu, s,  o);
        sq += __shfl_xor_sync(0xffffffffu, sq, o);
    }
    int warp = t >> 5, lane = t & 31;
    if (lane == 0) { ssum[warp] = s; ssq[warp] = sq; }
    __syncthreads();
    s = 0.f; sq = 0.f;
    #pragma unroll
    for (int i = 0; i < 8; i++) { s += ssum[i]; sq += ssq[i]; }

    float mu  = s * (1.0f/HH);
    float var = sq * (1.0f/HH) - mu*mu;
    float inv = rsqrtf(var + 1e-5f);

    float4 g  = ((const float4*)gamma)[t];
    float4 bt = ((const float4*)beta)[t];
    float o[4];
    o[0] = (v.x-mu)*inv*g.x + bt.x;
    o[1] = (v.y-mu)*inv*g.y + bt.y;
    o[2] = (v.z-mu)*inv*g.z + bt.z;
    o[3] = (v.w-mu)*inv*g.w + bt.w;

    size_t base = (size_t)row*HH + t*4;
    #pragma unroll
    for (int i = 0; i < 4; i++) {
        __nv_bfloat16 h = __float2bfloat16(o[i]);
        g_xn_hi[base+i] = h;
        g_xn_lo[base+i] = __float2bfloat16(o[i] - __bfloat162float(h));
    }
}

// ---------------------------------------------------------------------------
// Weight conversion fp32 -> bf16 hi/lo, all 4 W at once.
// ---------------------------------------------------------------------------
__global__ void convw_kernel(const float* __restrict__ Wq, const float* __restrict__ Wk,
                             const float* __restrict__ Wv, const float* __restrict__ Wo) {
    int i = blockIdx.x*blockDim.x + threadIdx.x;
    const int M = HH*HH;
    const float* src = (i < M) ? Wq : (i < 2*M) ? Wk : (i < 3*M) ? Wv : Wo;
    float x = src[i & (M-1)];
    __nv_bfloat16 h = __float2bfloat16(x);
    g_w_hi[i] = h;
    g_w_lo[i] = __float2bfloat16(x - __bfloat162float(h));
}

// ---------------------------------------------------------------------------
// Split-bf16 HMMA NT-GEMM with cp.async double buffering.
// 128x128 block tile, 8 warps (2m x 4n of 64x32), K-chunk 64.
// MODE 0: dst = q/k/v split bf16 head-layout (q pre-scaled). MODE 3: out+bias+resid.
// ---------------------------------------------------------------------------
template<int MODE>
__global__ __launch_bounds__(256, 1) void gemm_mma(const float* __restrict__ bo,
                                                   const float* __restrict__ resid,
                                                   float* __restrict__ out) {
    extern __shared__ char sm[];
    uint32_t smb = smem_u32(sm);

    int tid = threadIdx.x;
    int w = tid >> 5, lane = tid & 31;
    int wm = w & 1, wn = w >> 1;
    int row0 = blockIdx.y * 128;
    int col0 = blockIdx.x * 128;
    int widx = (MODE == 3) ? 3 : blockIdx.z;

    const __nv_bfloat16* Ahi = (MODE == 3) ? g_at_hi : g_xn_hi;
    const __nv_bfloat16* Alo = (MODE == 3) ? g_at_lo : g_xn_lo;
    const __nv_bfloat16* Bhi = g_w_hi + (size_t)widx*HH*HH;
    const __nv_bfloat16* Blo = g_w_lo + (size_t)widx*HH*HH;

    float acc[4][4][4];
    #pragma unroll
    for (int i = 0; i < 4; i++)
        #pragma unroll
        for (int j = 0; j < 4; j++)
            #pragma unroll
            for (int q = 0; q < 4; q++) acc[i][j][q] = 0.f;

    auto prefetch_chunk = [&](int chunk) {
        int kt = chunk * 64;
        uint32_t stg = smb + (uint32_t)(chunk & 1) * 65536u;
        #pragma unroll
        for (int t = 0; t < 16; t++) {
            int idx = tid + t*256;                // 0..4095 uint4 slots
            int a   = idx >> 10;                  // 0=Ahi 1=Alo 2=Bhi 3=Blo
            int e   = idx & 1023;
            int r   = e >> 3, c16 = e & 7;
            const __nv_bfloat16* src =
                (a == 0) ? Ahi + (size_t)(row0 + r)*HH + kt :
                (a == 1) ? Alo + (size_t)(row0 + r)*HH + kt :
                (a == 2) ? Bhi + (size_t)(col0 + r)*HH + kt :
                           Blo + (size_t)(col0 + r)*HH + kt;
            cpasync16(stg + (uint32_t)a*16384u + SWZ((uint32_t)(r*128 + c16*16)),
                      src + c16*8);
        }
        CP_COMMIT();
    };

    prefetch_chunk(0);

    int a_r  = wm*64 + ((lane >> 3) & 1)*8 + (lane & 7);
    int a_ks = (lane >> 4);
    int b_r  = wn*32 + ((lane >> 4) & 1)*8 + (lane & 7);
    int b_ks = ((lane >> 3) & 1);

    for (int chunk = 0; chunk < 16; ++chunk) {
        if (chunk + 1 < 16) { prefetch_chunk(chunk + 1); CP_WAIT(1); }
        else                { CP_WAIT(0); }
        __syncthreads();

        uint32_t st = smb + (uint32_t)(chunk & 1) * 65536u;

        #pragma unroll
        for (int k16 = 0; k16 < 4; ++k16) {
            int ksA = (a_ks + k16*2) * 16;
            int ksB = (b_ks + k16*2) * 16;

            uint32_t Af[4][4], Al[4][4], Bf[4][2], Bl[4][2];
            #pragma unroll
            for (int mf = 0; mf < 4; mf++) {
                uint32_t off = SWZ((uint32_t)((a_r + mf*16)*128 + ksA));
                ldsm4(Af[mf][0], Af[mf][1], Af[mf][2], Af[mf][3], st + off);
                ldsm4(Al[mf][0], Al[mf][1], Al[mf][2], Al[mf][3], st + 16384u + off);
            }
            #pragma unroll
            for (int nh = 0; nh < 2; nh++) {
                uint32_t off = SWZ((uint32_t)((b_r + nh*16)*128 + ksB));
                uint32_t r0, r1, r2, r3;
                ldsm4(r0, r1, r2, r3, st + 32768u + off);
                Bf[nh*2+0][0] = r0; Bf[nh*2+0][1] = r1;
                Bf[nh*2+1][0] = r2; Bf[nh*2+1][1] = r3;
                ldsm4(r0, r1, r2, r3, st + 49152u + off);
                Bl[nh*2+0][0] = r0; Bl[nh*2+0][1] = r1;
                Bl[nh*2+1][0] = r2; Bl[nh*2+1][1] = r3;
            }
            #pragma unroll
            for (int mf = 0; mf < 4; mf++)
                #pragma unroll
                for (int nf = 0; nf < 4; nf++) {
                    mma16816(acc[mf][nf], Af[mf], Bf[nf]);
                    mma16816(acc[mf][nf], Af[mf], Bl[nf]);
                    mma16816(acc[mf][nf], Al[mf], Bf[nf]);
                }
        }
        __syncthreads();
    }

    float qscale = (MODE < 3 && blockIdx.z == 0) ? 0.125f : 1.0f;
    #pragma unroll
    for (int mf = 0; mf < 4; mf++) {
        int mr = row0 + wm*64 + mf*16 + (lane >> 2);
        #pragma unroll
        for (int nf = 0; nf < 4; nf++) {
            int nc = col0 + wn*32 + nf*8 + (lane & 3)*2;
            #pragma unroll
            for (int half = 0; half < 2; half++) {
                int gi = mr + half*8;
                float v0 = acc[mf][nf][half*2 + 0];
                float v1 = acc[mf][nf][half*2 + 1];
                if (MODE < 3) {
                    v0 *= qscale; v1 *= qscale;
                    int b  = gi >> 11;
                    int s_ = gi & 2047;
                    int h  = nc >> 6;
                    int d  = nc & 63;
                    __nv_bfloat16* dhi = (blockIdx.z == 0) ? g_qhi : (blockIdx.z == 1) ? g_khi : g_vhi;
                    __nv_bfloat16* dlo = (blockIdx.z == 0) ? g_qlo : (blockIdx.z == 1) ? g_klo : g_vlo;
                    size_t base = (size_t)(((b << 4) + h)*SS + s_)*HDD + d;
                    __nv_bfloat16 h0 = __float2bfloat16(v0);
                    __nv_bfloat16 h1 = __float2bfloat16(v1);
                    *(__nv_bfloat162*)&dhi[base] = __halves2bfloat162(h0, h1);
                    *(__nv_bfloat162*)&dlo[base] = __halves2bfloat162(
                        __float2bfloat16(v0 - __bfloat162float(h0)),
                        __float2bfloat16(v1 - __bfloat162float(h1)));
                } else {
                    size_t base = (size_t)gi*HH + nc;
                    const float2 rr = *(const float2*)&resid[base];
                    float2* p = (float2*)&out[base];
                    *p = make_float2(v0 + bo[nc] + rr.x, v1 + bo[nc+1] + rr.y);
                }
            }
        }
    }
}

// ---------------------------------------------------------------------------
// HMMA flash attention, cp.async double-buffered.
// Block = (bh, 128-query tile), 8 warps x 16 q-rows; 64-key tiles, 32 iters.
// Smem: stage0 [0,32K), stage1 [32K,64K); each = Khi|Klo|Vhi|Vlo 8KB apiece.
// Q (128x64 hi/lo, 32KB) staged into stage0 before the pipeline starts.
// ---------------------------------------------------------------------------
__global__ __launch_bounds__(256) void attn_mma() {
    extern __shared__ char sm[];
    uint32_t smb = smem_u32(sm);

    int tid = threadIdx.x;
    int w = tid >> 5, lane = tid & 31;
    int bh = blockIdx.y;
    int qt = blockIdx.x;              // 0..15 (128-query tiles)
    size_t bhoff = (size_t)bh*SS*HDD;

    // ---- stage Q tile (128x64 hi/lo) into stage0, then preload A-fragments ----
    {
        const __nv_bfloat16* Qh = g_qhi + bhoff + (size_t)qt*128*HDD;
        const __nv_bfloat16* Ql = g_qlo + bhoff + (size_t)qt*128*HDD;
        #pragma unroll
        for (int t = 0; t < 8; t++) {
            int idx = tid + t*256;            // 0..2047 uint4 slots
            int a   = idx >> 10;              // 0=hi,1=lo
            int e   = idx & 1023;
            int r   = e >> 3, c16 = e & 7;
            const __nv_bfloat16* src = (a ? Ql : Qh) + (size_t)r*HDD + c16*8;
            cpasync16(smb + (uint32_t)a*16384u + SWZ((uint32_t)(r*128 + c16*16)), src);
        }
        CP_COMMIT();
        CP_WAIT(0);
    }
    __syncthreads();

    uint32_t qh[4][4], ql[4][4];
    {
        int a_r  = w*16 + ((lane >> 3) & 1)*8 + (lane & 7);
        int a_ks = (lane >> 4);
        #pragma unroll
        for (int k16 = 0; k16 < 4; k16++) {
            uint32_t off = SWZ((uint32_t)(a_r*128 + (a_ks + k16*2)*16));
            ldsm4(qh[k16][0], qh[k16][1], qh[k16][2], qh[k16][3], smb + off);
            ldsm4(ql[k16][0], ql[k16][1], ql[k16][2], ql[k16][3], smb + 16384u + off);
        }
    }
    __syncthreads();   // all warps done reading Q before stage0 is overwritten

    const __nv_bfloat16* Kh = g_khi + bhoff;
    const __nv_bfloat16* Kl = g_klo + bhoff;
    const __nv_bfloat16* Vh = g_vhi + bhoff;
    const __nv_bfloat16* Vl = g_vlo + bhoff;

    auto prefetch_tile = [&](int kt) {
        uint32_t stg = smb + (uint32_t)(kt & 1) * 32768u;
        #pragma unroll
        for (int t = 0; t < 8; t++) {
            int idx = tid + t*256;            // 0..2047 uint4 slots
            int a   = idx >> 9;               // 0=Khi 1=Klo 2=Vhi 3=Vlo
            int e   = idx & 511;
            int r   = e >> 3, c16 = e & 7;
            const __nv_bfloat16* src =
                ((a == 0) ? Kh : (a == 1) ? Kl : (a == 2) ? Vh : Vl)
                + (size_t)(kt*64 + r)*HDD + c16*8;
            cpasync16(stg + (uint32_t)a*8192u + SWZ((uint32_t)(r*128 + c16*16)), src);
        }
        CP_COMMIT();
    };

    float m0 = -1e30f, m1 = -1e30f, l0 = 0.f, l1 = 0.f;
    float O[8][4];
    #pragma unroll
    for (int n = 0; n < 8; n++)
        #pragma unroll
        for (int q = 0; q < 4; q++) O[n][q] = 0.f;

    int kb_row = ((lane >> 4) & 1)*8 + (lane & 7);
    int kb_k   = ((lane >> 3) & 1);
    int v_row  = ((lane >> 3) & 1)*8 + (lane & 7);
    int v_col  = ((lane >> 4) & 1)*8;

    prefetch_tile(0);

    for (int kt = 0; kt < SS/64; kt++) {
        if (kt + 1 < SS/64) { prefetch_tile(kt + 1); CP_WAIT(1); }
        else                { CP_WAIT(0); }
        __syncthreads();

        uint32_t st = smb + (uint32_t)(kt & 1) * 32768u;

        // ---- S = Q K^T (3-term split) ----
        float s[8][4];
        #pragma unroll
        for (int n = 0; n < 8; n++)
            #pragma unroll
            for (int q = 0; q < 4; q++) s[n][q] = 0.f;

        #pragma unroll
        for (int k16 = 0; k16 < 4; k16++) {
            uint32_t Bh_[8][2], Bl_[8][2];
            #pragma unroll
            for (int np = 0; np < 4; np++) {
                uint32_t off = SWZ((uint32_t)((np*16 + kb_row)*128 + (kb_k + k16*2)*16));
                uint32_t r0, r1, r2, r3;
                ldsm4(r0, r1, r2, r3, st + off);
                Bh_[np*2+0][0] = r0; Bh_[np*2+0][1] = r1;
                Bh_[np*2+1][0] = r2; Bh_[np*2+1][1] = r3;
                ldsm4(r0, r1, r2, r3, st + 8192u + off);
                Bl_[np*2+0][0] = r0; Bl_[np*2+0][1] = r1;
                Bl_[np*2+1][0] = r2; Bl_[np*2+1][1] = r3;
            }
            #pragma unroll
            for (int n = 0; n < 8; n++) {
                mma16816(s[n], qh[k16], Bh_[n]);
                mma16816(s[n], qh[k16], Bl_[n]);
                mma16816(s[n], ql[k16], Bh_[n]);
            }
        }

        // ---- online softmax (rows g=lane>>2 and g+8; quad shuffles) ----
        float mx0 = -1e30f, mx1 = -1e30f;
        #pragma unroll
        for (int n = 0; n < 8; n++) {
            mx0 = fmaxf(mx0, fmaxf(s[n][0], s[n][1]));
            mx1 = fmaxf(mx1, fmaxf(s[n][2], s[n][3]));
        }
        mx0 = fmaxf(mx0, __shfl_xor_sync(0xffffffffu, mx0, 1, 4));
        mx0 = fmaxf(mx0, __shfl_xor_sync(0xffffffffu, mx0, 2, 4));
        mx1 = fmaxf(mx1, __shfl_xor_sync(0xffffffffu, mx1, 1, 4));
        mx1 = fmaxf(mx1, __shfl_xor_sync(0xffffffffu, mx1, 2, 4));
        float m0n = fmaxf(m0, mx0), m1n = fmaxf(m1, mx1);
        float c0 = __expf(m0 - m0n), c1 = __expf(m1 - m1n);
        m0 = m0n; m1 = m1n;

        float rs0 = 0.f, rs1 = 0.f;
        #pragma unroll
        for (int n = 0; n < 8; n++) {
            s[n][0] = __expf(s[n][0] - m0); rs0 += s[n][0];
            s[n][1] = __expf(s[n][1] - m0); rs0 += s[n][1];
            s[n][2] = __expf(s[n][2] - m1); rs1 += s[n][2];
            s[n][3] = __expf(s[n][3] - m1); rs1 += s[n][3];
        }
        rs0 += __shfl_xor_sync(0xffffffffu, rs0, 1, 4);
        rs0 += __shfl_xor_sync(0xffffffffu, rs0, 2, 4);
        rs1 += __shfl_xor_sync(0xffffffffu, rs1, 1, 4);
        rs1 += __shfl_xor_sync(0xffffffffu, rs1, 2, 4);
        l0 = l0*c0 + rs0;
        l1 = l1*c1 + rs1;
        #pragma unroll
        for (int n = 0; n < 8; n++) {
            O[n][0] *= c0; O[n][1] *= c0; O[n][2] *= c1; O[n][3] *= c1;
        }

        // ---- O += P V (3-term split; P from s via C->A fragment identity) ----
        #pragma unroll
        for (int k16 = 0; k16 < 4; k16++) {
            float p00 = s[2*k16][0],   p01 = s[2*k16][1];
            float p02 = s[2*k16][2],   p03 = s[2*k16][3];
            float p10 = s[2*k16+1][0], p11 = s[2*k16+1][1];
            float p12 = s[2*k16+1][2], p13 = s[2*k16+1][3];
            float h00 = bfh(p00), h01 = bfh(p01), h02 = bfh(p02), h03 = bfh(p03);
            float h10 = bfh(p10), h11 = bfh(p11), h12 = bfh(p12), h13 = bfh(p13);
            uint32_t ph[4], pl[4];
            ph[0] = packbf(h00, h01);           ph[1] = packbf(h02, h03);
            ph[2] = packbf(h10, h11);           ph[3] = packbf(h12, h13);
            pl[0] = packbf(p00-h00, p01-h01);   pl[1] = packbf(p02-h02, p03-h03);
            pl[2] = packbf(p10-h10, p11-h11);   pl[3] = packbf(p12-h12, p13-h13);

            uint32_t vh[8][2], vl[8][2];
            #pragma unroll
            for (int np = 0; np < 4; np++) {
                uint32_t off = SWZ((uint32_t)((k16*16 + v_row)*128 + (np*16 + v_col)*2));
                uint32_t r0, r1, r2, r3;
                ldsm4t(r0, r1, r2, r3, st + 16384u + off);
                vh[np*2+0][0] = r0; vh[np*2+0][1] = r1;
                vh[np*2+1][0] = r2; vh[np*2+1][1] = r3;
                ldsm4t(r0, r1, r2, r3, st + 24576u + off);
                vl[np*2+0][0] = r0; vl[np*2+0][1] = r1;
                vl[np*2+1][0] = r2; vl[np*2+1][1] = r3;
            }
            #pragma unroll
            for (int n = 0; n < 8; n++) {
                mma16816(O[n], ph, vh[n]);
                mma16816(O[n], ph, vl[n]);
                mma16816(O[n], pl, vh[n]);
            }
        }
        __syncthreads();
    }

    // ---- epilogue: O/l -> g_at hi/lo, [B,S,H] with head offset ----
    int b = bh >> 4, h = bh & 15;
    float inv0 = 1.0f / l0, inv1 = 1.0f / l1;
    int gi0 = b*SS + qt*128 + w*16 + (lane >> 2);
    int col = h*64 + (lane & 3)*2;
    #pragma unroll
    for (int n = 0; n < 8; n++) {
        #pragma unroll
        for (int half = 0; half < 2; half++) {
            int gi = gi0 + half*8;
            float v0 = O[n][half*2+0] * (half ? inv1 : inv0);
            float v1 = O[n][half*2+1] * (half ? inv1 : inv0);
            size_t idx = (size_t)gi*HH + col + n*8;
            __nv_bfloat16 h0 = __float2bfloat16(v0);
            __nv_bfloat16 h1 = __float2bfloat16(v1);
            *(__nv_bfloat162*)&g_at_hi[idx] = __halves2bfloat162(h0, h1);
            *(__nv_bfloat162*)&g_at_lo[idx] = __halves2bfloat162(
                __float2bfloat16(v0 - __bfloat162float(h0)),
                __float2bfloat16(v1 - __bfloat162float(h1)));
        }
    }
}

// ---------------------------------------------------------------------------
extern "C" void kernel_launch(void* const* d_in, const int* in_sizes, int n_in,
                              void* d_out, int out_size) {
    const float* x     = (const float*)d_in[0];
    const float* Wq    = (const float*)d_in[1];
    const float* Wk    = (const float*)d_in[2];
    const float* Wv    = (const float*)d_in[3];
    const float* Wo    = (const float*)d_in[4];
    const float* bo    = (const float*)d_in[5];
    const float* gamma = (const float*)d_in[6];
    const float* beta  = (const float*)d_in[7];
    float* out = (float*)d_out;

    ln_kernel<<<RR, 256>>>(x, gamma, beta);
    convw_kernel<<<(4*HH*HH)/256, 256>>>(Wq, Wk, Wv, Wo);

    const int GSMEM = 2*65536;
    cudaFuncSetAttribute(gemm_mma<0>, cudaFuncAttributeMaxDynamicSharedMemorySize, GSMEM);
    cudaFuncSetAttribute(gemm_mma<3>, cudaFuncAttributeMaxDynamicSharedMemorySize, GSMEM);

    gemm_mma<0><<<dim3(HH/128, RR/128, 3), 256, GSMEM>>>(nullptr, nullptr, nullptr);

    const int ASMEM = 65536;
    cudaFuncSetAttribute(attn_mma, cudaFuncAttributeMaxDynamicSharedMemorySize, ASMEM);
    attn_mma<<<dim3(SS/128, BB*NHH), 256, ASMEM>>>();

    gemm_mma<3><<<dim3(HH/128, RR/128, 1), 256, GSMEM>>>(bo, x, out);
}

// round 11
// speedup vs baseline: 3.7443x; 1.0210x over previous
#include <cuda_runtime.h>
#include <cuda_bf16.h>
#include <cstdint>
#include <math.h>

#define HH   1024
#define NHH  16
#define HDD  64
#define BB   2
#define SS   2048
#define RR   (BB*SS)   // 4096 rows

// ---------------- device scratch (no allocations allowed) -------------------
__device__ __nv_bfloat16 g_qhi[RR*HH], g_qlo[RR*HH];   // [B*NH, S, HD], pre-scaled 0.125
__device__ __nv_bfloat16 g_khi[RR*HH], g_klo[RR*HH];
__device__ __nv_bfloat16 g_vhi[RR*HH], g_vlo[RR*HH];
__device__ __nv_bfloat16 g_xn_hi[RR*HH], g_xn_lo[RR*HH];     // LN output split
__device__ __nv_bfloat16 g_w_hi[4*HH*HH], g_w_lo[4*HH*HH];   // Wq,Wk,Wv,Wo split
__device__ __nv_bfloat16 g_at_hi[RR*HH], g_at_lo[RR*HH];     // attention out split

// ---------------- helpers ---------------------------------------------------
__device__ __forceinline__ uint32_t smem_u32(const void* p) {
    uint32_t a;
    asm("{ .reg .u64 t; cvta.to.shared.u64 t, %1; cvt.u32.u64 %0, t; }" : "=r"(a) : "l"(p));
    return a;
}
#define SWZ(o)   ((o) ^ (((o) >> 3) & 0x70))   // 128B-row swizzle
#define SWZ64(o) ((o) ^ (((o) >> 3) & 0x30))   // 64B-row swizzle

__device__ __forceinline__ void cpasync16(uint32_t dst, const void* src) {
    asm volatile("cp.async.cg.shared.global [%0], [%1], 16;" :: "r"(dst), "l"(src));
}
#define CP_COMMIT() asm volatile("cp.async.commit_group;" ::: "memory")
#define CP_WAIT(n)  asm volatile("cp.async.wait_group %0;" :: "n"(n) : "memory")

__device__ __forceinline__ void ldsm4(uint32_t& r0, uint32_t& r1, uint32_t& r2, uint32_t& r3,
                                      uint32_t a) {
    asm volatile("ldmatrix.sync.aligned.m8n8.x4.shared.b16 {%0,%1,%2,%3}, [%4];"
                 : "=r"(r0), "=r"(r1), "=r"(r2), "=r"(r3) : "r"(a));
}
__device__ __forceinline__ void ldsm4t(uint32_t& r0, uint32_t& r1, uint32_t& r2, uint32_t& r3,
                                       uint32_t a) {
    asm volatile("ldmatrix.sync.aligned.m8n8.x4.trans.shared.b16 {%0,%1,%2,%3}, [%4];"
                 : "=r"(r0), "=r"(r1), "=r"(r2), "=r"(r3) : "r"(a));
}
__device__ __forceinline__ void mma16816(float* c, const uint32_t* a, const uint32_t* b) {
    asm volatile("mma.sync.aligned.m16n8k16.row.col.f32.bf16.bf16.f32 "
                 "{%0,%1,%2,%3}, {%4,%5,%6,%7}, {%8,%9}, {%0,%1,%2,%3};"
                 : "+f"(c[0]), "+f"(c[1]), "+f"(c[2]), "+f"(c[3])
                 : "r"(a[0]), "r"(a[1]), "r"(a[2]), "r"(a[3]), "r"(b[0]), "r"(b[1]));
}
__device__ __forceinline__ uint32_t packbf(float p0, float p1) {
    uint32_t r;
    asm("cvt.rn.bf16x2.f32 %0, %1, %2;" : "=r"(r) : "f"(p1), "f"(p0));
    return r;
}
__device__ __forceinline__ float bfh(float x) {
    return __bfloat162float(__float2bfloat16(x));
}

// ---------------------------------------------------------------------------
// LayerNorm: one block per row, 256 threads, float4 per thread; emits bf16 hi/lo.
// ---------------------------------------------------------------------------
__global__ void ln_kernel(const float* __restrict__ x,
                          const float* __restrict__ gamma,
                          const float* __restrict__ beta) {
    int row = blockIdx.x;
    int t   = threadIdx.x;
    const float4* xr = (const float4*)(x + (size_t)row*HH);
    float4 v = xr[t];
    float s  = v.x + v.y + v.z + v.w;
    float sq = v.x*v.x + v.y*v.y + v.z*v.z + v.w*v.w;

    __shared__ float ssum[8], ssq[8];
    #pragma unroll
    for (int o = 16; o >= 1; o >>= 1) {
        s  += __shfl_xor_sync(0xffffffffu, s,  o);
        sq += __shfl_xor_sync(0xffffffffu, sq, o);
    }
    int warp = t >> 5, lane = t & 31;
    if (lane == 0) { ssum[warp] = s; ssq[warp] = sq; }
    __syncthreads();
    s = 0.f; sq = 0.f;
    #pragma unroll
    for (int i = 0; i < 8; i++) { s += ssum[i]; sq += ssq[i]; }

    float mu  = s * (1.0f/HH);
    float var = sq * (1.0f/HH) - mu*mu;
    float inv = rsqrtf(var + 1e-5f);

    float4 g  = ((const float4*)gamma)[t];
    float4 bt = ((const float4*)beta)[t];
    float o[4];
    o[0] = (v.x-mu)*inv*g.x + bt.x;
    o[1] = (v.y-mu)*inv*g.y + bt.y;
    o[2] = (v.z-mu)*inv*g.z + bt.z;
    o[3] = (v.w-mu)*inv*g.w + bt.w;

    size_t base = (size_t)row*HH + t*4;
    #pragma unroll
    for (int i = 0; i < 4; i++) {
        __nv_bfloat16 h = __float2bfloat16(o[i]);
        g_xn_hi[base+i] = h;
        g_xn_lo[base+i] = __float2bfloat16(o[i] - __bfloat162float(h));
    }
}

// ---------------------------------------------------------------------------
// Weight conversion fp32 -> bf16 hi/lo, all 4 W at once.
// ---------------------------------------------------------------------------
__global__ void convw_kernel(const float* __restrict__ Wq, const float* __restrict__ Wk,
                             const float* __restrict__ Wv, const float* __restrict__ Wo) {
    int i = blockIdx.x*blockDim.x + threadIdx.x;
    const int M = HH*HH;
    const float* src = (i < M) ? Wq : (i < 2*M) ? Wk : (i < 3*M) ? Wv : Wo;
    float x = src[i & (M-1)];
    __nv_bfloat16 h = __float2bfloat16(x);
    g_w_hi[i] = h;
    g_w_lo[i] = __float2bfloat16(x - __bfloat162float(h));
}

// ---------------------------------------------------------------------------
// Split-bf16 HMMA NT-GEMM, cp.async double-buffered, K-chunk 32 (SW64 tiles).
// Stage = 4 tiles (Ahi|Alo|Bhi|Blo) of 128x32 bf16 = 8KB each -> 32KB; x2 = 64KB.
// 2 CTAs/SM. 8 warps (2m x 4n of 64x32).
// MODE 0: dst = q/k/v split bf16 head-layout (q pre-scaled). MODE 3: out+bias+resid.
// ---------------------------------------------------------------------------
template<int MODE>
__global__ __launch_bounds__(256, 2) void gemm_mma(const float* __restrict__ bo,
                                                   const float* __restrict__ resid,
                                                   float* __restrict__ out) {
    extern __shared__ char sm[];
    uint32_t smb = smem_u32(sm);

    int tid = threadIdx.x;
    int w = tid >> 5, lane = tid & 31;
    int wm = w & 1, wn = w >> 1;
    int row0 = blockIdx.y * 128;
    int col0 = blockIdx.x * 128;
    int widx = (MODE == 3) ? 3 : blockIdx.z;

    const __nv_bfloat16* Ahi = (MODE == 3) ? g_at_hi : g_xn_hi;
    const __nv_bfloat16* Alo = (MODE == 3) ? g_at_lo : g_xn_lo;
    const __nv_bfloat16* Bhi = g_w_hi + (size_t)widx*HH*HH;
    const __nv_bfloat16* Blo = g_w_lo + (size_t)widx*HH*HH;

    float acc[4][4][4];
    #pragma unroll
    for (int i = 0; i < 4; i++)
        #pragma unroll
        for (int j = 0; j < 4; j++)
            #pragma unroll
            for (int q = 0; q < 4; q++) acc[i][j][q] = 0.f;

    auto prefetch_chunk = [&](int chunk) {
        int kt = chunk * 32;
        uint32_t stg = smb + (uint32_t)(chunk & 1) * 32768u;
        #pragma unroll
        for (int t = 0; t < 8; t++) {
            int idx = tid + t*256;                // 0..2047 16B slots
            int a   = idx >> 9;                   // 0=Ahi 1=Alo 2=Bhi 3=Blo
            int e   = idx & 511;
            int r   = e >> 2, seg = e & 3;        // 128 rows x 4 segs of 8 bf16
            const __nv_bfloat16* src =
                (a == 0) ? Ahi + (size_t)(row0 + r)*HH + kt :
                (a == 1) ? Alo + (size_t)(row0 + r)*HH + kt :
                (a == 2) ? Bhi + (size_t)(col0 + r)*HH + kt :
                           Blo + (size_t)(col0 + r)*HH + kt;
            cpasync16(stg + (uint32_t)a*8192u + SWZ64((uint32_t)(r*64 + seg*16)),
                      src + seg*8);
        }
        CP_COMMIT();
    };

    prefetch_chunk(0);

    int a_r  = wm*64 + ((lane >> 3) & 1)*8 + (lane & 7);
    int a_ks = (lane >> 4);
    int b_r  = wn*32 + ((lane >> 4) & 1)*8 + (lane & 7);
    int b_ks = ((lane >> 3) & 1);

    for (int chunk = 0; chunk < 32; ++chunk) {
        if (chunk + 1 < 32) { prefetch_chunk(chunk + 1); CP_WAIT(1); }
        else                { CP_WAIT(0); }
        __syncthreads();

        uint32_t st = smb + (uint32_t)(chunk & 1) * 32768u;

        #pragma unroll
        for (int kk = 0; kk < 2; ++kk) {
            int sgA = (kk*2 + a_ks) * 16;
            int sgB = (kk*2 + b_ks) * 16;

            uint32_t Af[4][4], Al[4][4], Bf[4][2], Bl[4][2];
            #pragma unroll
            for (int mf = 0; mf < 4; mf++) {
                uint32_t off = SWZ64((uint32_t)((a_r + mf*16)*64 + sgA));
                ldsm4(Af[mf][0], Af[mf][1], Af[mf][2], Af[mf][3], st + off);
                ldsm4(Al[mf][0], Al[mf][1], Al[mf][2], Al[mf][3], st + 8192u + off);
            }
            #pragma unroll
            for (int nh = 0; nh < 2; nh++) {
                uint32_t off = SWZ64((uint32_t)((b_r + nh*16)*64 + sgB));
                uint32_t r0, r1, r2, r3;
                ldsm4(r0, r1, r2, r3, st + 16384u + off);
                Bf[nh*2+0][0] = r0; Bf[nh*2+0][1] = r1;
                Bf[nh*2+1][0] = r2; Bf[nh*2+1][1] = r3;
                ldsm4(r0, r1, r2, r3, st + 24576u + off);
                Bl[nh*2+0][0] = r0; Bl[nh*2+0][1] = r1;
                Bl[nh*2+1][0] = r2; Bl[nh*2+1][1] = r3;
            }
            #pragma unroll
            for (int mf = 0; mf < 4; mf++)
                #pragma unroll
                for (int nf = 0; nf < 4; nf++) {
                    mma16816(acc[mf][nf], Af[mf], Bf[nf]);
                    mma16816(acc[mf][nf], Af[mf], Bl[nf]);
                    mma16816(acc[mf][nf], Al[mf], Bf[nf]);
                }
        }
        __syncthreads();
    }

    float qscale = (MODE < 3 && blockIdx.z == 0) ? 0.125f : 1.0f;
    #pragma unroll
    for (int mf = 0; mf < 4; mf++) {
        int mr = row0 + wm*64 + mf*16 + (lane >> 2);
        #pragma unroll
        for (int nf = 0; nf < 4; nf++) {
            int nc = col0 + wn*32 + nf*8 + (lane & 3)*2;
            #pragma unroll
            for (int half = 0; half < 2; half++) {
                int gi = mr + half*8;
                float v0 = acc[mf][nf][half*2 + 0];
                float v1 = acc[mf][nf][half*2 + 1];
                if (MODE < 3) {
                    v0 *= qscale; v1 *= qscale;
                    int b  = gi >> 11;
                    int s_ = gi & 2047;
                    int h  = nc >> 6;
                    int d  = nc & 63;
                    __nv_bfloat16* dhi = (blockIdx.z == 0) ? g_qhi : (blockIdx.z == 1) ? g_khi : g_vhi;
                    __nv_bfloat16* dlo = (blockIdx.z == 0) ? g_qlo : (blockIdx.z == 1) ? g_klo : g_vlo;
                    size_t base = (size_t)(((b << 4) + h)*SS + s_)*HDD + d;
                    __nv_bfloat16 h0 = __float2bfloat16(v0);
                    __nv_bfloat16 h1 = __float2bfloat16(v1);
                    *(__nv_bfloat162*)&dhi[base] = __halves2bfloat162(h0, h1);
                    *(__nv_bfloat162*)&dlo[base] = __halves2bfloat162(
                        __float2bfloat16(v0 - __bfloat162float(h0)),
                        __float2bfloat16(v1 - __bfloat162float(h1)));
                } else {
                    size_t base = (size_t)gi*HH + nc;
                    const float2 rr = *(const float2*)&resid[base];
                    float2* p = (float2*)&out[base];
                    *p = make_float2(v0 + bo[nc] + rr.x, v1 + bo[nc+1] + rr.y);
                }
            }
        }
    }
}

// ---------------------------------------------------------------------------
// HMMA flash attention, cp.async double-buffered, 2 CTAs/SM target.
// Block = (bh, 128-query tile), 8 warps x 16 q-rows; 64-key tiles, 32 iters.
// Smem: stage0 [0,32K), stage1 [32K,64K); each = Khi|Klo|Vhi|Vlo 8KB apiece.
// Q (128x64 hi/lo, 32KB) staged into stage0 before the pipeline starts.
// ---------------------------------------------------------------------------
__global__ __launch_bounds__(256, 2) void attn_mma() {
    extern __shared__ char sm[];
    uint32_t smb = smem_u32(sm);

    int tid = threadIdx.x;
    int w = tid >> 5, lane = tid & 31;
    int bh = blockIdx.y;
    int qt = blockIdx.x;              // 0..15 (128-query tiles)
    size_t bhoff = (size_t)bh*SS*HDD;

    // ---- stage Q tile (128x64 hi/lo) into stage0, then preload A-fragments ----
    {
        const __nv_bfloat16* Qh = g_qhi + bhoff + (size_t)qt*128*HDD;
        const __nv_bfloat16* Ql = g_qlo + bhoff + (size_t)qt*128*HDD;
        #pragma unroll
        for (int t = 0; t < 8; t++) {
            int idx = tid + t*256;            // 0..2047 uint4 slots
            int a   = idx >> 10;              // 0=hi,1=lo
            int e   = idx & 1023;
            int r   = e >> 3, c16 = e & 7;
            const __nv_bfloat16* src = (a ? Ql : Qh) + (size_t)r*HDD + c16*8;
            cpasync16(smb + (uint32_t)a*16384u + SWZ((uint32_t)(r*128 + c16*16)), src);
        }
        CP_COMMIT();
        CP_WAIT(0);
    }
    __syncthreads();

    uint32_t qh[4][4], ql[4][4];
    {
        int a_r  = w*16 + ((lane >> 3) & 1)*8 + (lane & 7);
        int a_ks = (lane >> 4);
        #pragma unroll
        for (int k16 = 0; k16 < 4; k16++) {
            uint32_t off = SWZ((uint32_t)(a_r*128 + (a_ks + k16*2)*16));
            ldsm4(qh[k16][0], qh[k16][1], qh[k16][2], qh[k16][3], smb + off);
            ldsm4(ql[k16][0], ql[k16][1], ql[k16][2], ql[k16][3], smb + 16384u + off);
        }
    }
    __syncthreads();   // all warps done reading Q before stage0 is overwritten

    const __nv_bfloat16* Kh = g_khi + bhoff;
    const __nv_bfloat16* Kl = g_klo + bhoff;
    const __nv_bfloat16* Vh = g_vhi + bhoff;
    const __nv_bfloat16* Vl = g_vlo + bhoff;

    auto prefetch_tile = [&](int kt) {
        uint32_t stg = smb + (uint32_t)(kt & 1) * 32768u;
        #pragma unroll
        for (int t = 0; t < 8; t++) {
            int idx = tid + t*256;            // 0..2047 uint4 slots
            int a   = idx >> 9;               // 0=Khi 1=Klo 2=Vhi 3=Vlo
            int e   = idx & 511;
            int r   = e >> 3, c16 = e & 7;
            const __nv_bfloat16* src =
                ((a == 0) ? Kh : (a == 1) ? Kl : (a == 2) ? Vh : Vl)
                + (size_t)(kt*64 + r)*HDD + c16*8;
            cpasync16(stg + (uint32_t)a*8192u + SWZ((uint32_t)(r*128 + c16*16)), src);
        }
        CP_COMMIT();
    };

    float m0 = -1e30f, m1 = -1e30f, l0 = 0.f, l1 = 0.f;
    float O[8][4];
    #pragma unroll
    for (int n = 0; n < 8; n++)
        #pragma unroll
        for (int q = 0; q < 4; q++) O[n][q] = 0.f;

    int kb_row = ((lane >> 4) & 1)*8 + (lane & 7);
    int kb_k   = ((lane >> 3) & 1);
    int v_row  = ((lane >> 3) & 1)*8 + (lane & 7);
    int v_col  = ((lane >> 4) & 1)*8;

    prefetch_tile(0);

    for (int kt = 0; kt < SS/64; kt++) {
        if (kt + 1 < SS/64) { prefetch_tile(kt + 1); CP_WAIT(1); }
        else                { CP_WAIT(0); }
        __syncthreads();

        uint32_t st = smb + (uint32_t)(kt & 1) * 32768u;

        // ---- S = Q K^T (3-term split); per-np fragment loads to cut reg peak ----
        float s[8][4];
        #pragma unroll
        for (int n = 0; n < 8; n++)
            #pragma unroll
            for (int q = 0; q < 4; q++) s[n][q] = 0.f;

        #pragma unroll
        for (int k16 = 0; k16 < 4; k16++) {
            #pragma unroll
            for (int np = 0; np < 4; np++) {
                uint32_t off = SWZ((uint32_t)((np*16 + kb_row)*128 + (kb_k + k16*2)*16));
                uint32_t bh0, bh1, bh2, bh3, bl0, bl1, bl2, bl3;
                ldsm4(bh0, bh1, bh2, bh3, st + off);
                ldsm4(bl0, bl1, bl2, bl3, st + 8192u + off);
                uint32_t bhi[2], bli[2];
                bhi[0] = bh0; bhi[1] = bh1; bli[0] = bl0; bli[1] = bl1;
                mma16816(s[np*2+0], qh[k16], bhi);
                mma16816(s[np*2+0], qh[k16], bli);
                mma16816(s[np*2+0], ql[k16], bhi);
                bhi[0] = bh2; bhi[1] = bh3; bli[0] = bl2; bli[1] = bl3;
                mma16816(s[np*2+1], qh[k16], bhi);
                mma16816(s[np*2+1], qh[k16], bli);
                mma16816(s[np*2+1], ql[k16], bhi);
            }
        }

        // ---- online softmax (rows g=lane>>2 and g+8; quad shuffles) ----
        float mx0 = -1e30f, mx1 = -1e30f;
        #pragma unroll
        for (int n = 0; n < 8; n++) {
            mx0 = fmaxf(mx0, fmaxf(s[n][0], s[n][1]));
            mx1 = fmaxf(mx1, fmaxf(s[n][2], s[n][3]));
        }
        mx0 = fmaxf(mx0, __shfl_xor_sync(0xffffffffu, mx0, 1, 4));
        mx0 = fmaxf(mx0, __shfl_xor_sync(0xffffffffu, mx0, 2, 4));
        mx1 = fmaxf(mx1, __shfl_xor_sync(0xffffffffu, mx1, 1, 4));
        mx1 = fmaxf(mx1, __shfl_xor_sync(0xffffffffu, mx1, 2, 4));
        float m0n = fmaxf(m0, mx0), m1n = fmaxf(m1, mx1);
        float c0 = __expf(m0 - m0n), c1 = __expf(m1 - m1n);
        m0 = m0n; m1 = m1n;

        float rs0 = 0.f, rs1 = 0.f;
        #pragma unroll
        for (int n = 0; n < 8; n++) {
            s[n][0] = __expf(s[n][0] - m0); rs0 += s[n][0];
            s[n][1] = __expf(s[n][1] - m0); rs0 += s[n][1];
            s[n][2] = __expf(s[n][2] - m1); rs1 += s[n][2];
            s[n][3] = __expf(s[n][3] - m1); rs1 += s[n][3];
        }
        rs0 += __shfl_xor_sync(0xffffffffu, rs0, 1, 4);
        rs0 += __shfl_xor_sync(0xffffffffu, rs0, 2, 4);
        rs1 += __shfl_xor_sync(0xffffffffu, rs1, 1, 4);
        rs1 += __shfl_xor_sync(0xffffffffu, rs1, 2, 4);
        l0 = l0*c0 + rs0;
        l1 = l1*c1 + rs1;
        #pragma unroll
        for (int n = 0; n < 8; n++) {
            O[n][0] *= c0; O[n][1] *= c0; O[n][2] *= c1; O[n][3] *= c1;
        }

        // ---- O += P V (3-term split; P from s via C->A fragment identity) ----
        #pragma unroll
        for (int k16 = 0; k16 < 4; k16++) {
            float p00 = s[2*k16][0],   p01 = s[2*k16][1];
            float p02 = s[2*k16][2],   p03 = s[2*k16][3];
            float p10 = s[2*k16+1][0], p11 = s[2*k16+1][1];
            float p12 = s[2*k16+1][2], p13 = s[2*k16+1][3];
            float h00 = bfh(p00), h01 = bfh(p01), h02 = bfh(p02), h03 = bfh(p03);
            float h10 = bfh(p10), h11 = bfh(p11), h12 = bfh(p12), h13 = bfh(p13);
            uint32_t ph[4], pl[4];
            ph[0] = packbf(h00, h01);           ph[1] = packbf(h02, h03);
            ph[2] = packbf(h10, h11);           ph[3] = packbf(h12, h13);
            pl[0] = packbf(p00-h00, p01-h01);   pl[1] = packbf(p02-h02, p03-h03);
            pl[2] = packbf(p10-h10, p11-h11);   pl[3] = packbf(p12-h12, p13-h13);

            #pragma unroll
            for (int np = 0; np < 4; np++) {
                uint32_t off = SWZ((uint32_t)((k16*16 + v_row)*128 + (np*16 + v_col)*2));
                uint32_t vh0, vh1, vh2, vh3, vl0, vl1, vl2, vl3;
                ldsm4t(vh0, vh1, vh2, vh3, st + 16384u + off);
                ldsm4t(vl0, vl1, vl2, vl3, st + 24576u + off);
                uint32_t vhi[2], vli[2];
                vhi[0] = vh0; vhi[1] = vh1; vli[0] = vl0; vli[1] = vl1;
                mma16816(O[np*2+0], ph, vhi);
                mma16816(O[np*2+0], ph, vli);
                mma16816(O[np*2+0], pl, vhi);
                vhi[0] = vh2; vhi[1] = vh3; vli[0] = vl2; vli[1] = vl3;
                mma16816(O[np*2+1], ph, vhi);
                mma16816(O[np*2+1], ph, vli);
                mma16816(O[np*2+1], pl, vhi);
            }
        }
        __syncthreads();
    }

    // ---- epilogue: O/l -> g_at hi/lo, [B,S,H] with head offset ----
    int b = bh >> 4, h = bh & 15;
    float inv0 = 1.0f / l0, inv1 = 1.0f / l1;
    int gi0 = b*SS + qt*128 + w*16 + (lane >> 2);
    int col = h*64 + (lane & 3)*2;
    #pragma unroll
    for (int n = 0; n < 8; n++) {
        #pragma unroll
        for (int half = 0; half < 2; half++) {
            int gi = gi0 + half*8;
            float v0 = O[n][half*2+0] * (half ? inv1 : inv0);
            float v1 = O[n][half*2+1] * (half ? inv1 : inv0);
            size_t idx = (size_t)gi*HH + col + n*8;
            __nv_bfloat16 h0 = __float2bfloat16(v0);
            __nv_bfloat16 h1 = __float2bfloat16(v1);
            *(__nv_bfloat162*)&g_at_hi[idx] = __halves2bfloat162(h0, h1);
            *(__nv_bfloat162*)&g_at_lo[idx] = __halves2bfloat162(
                __float2bfloat16(v0 - __bfloat162float(h0)),
                __float2bfloat16(v1 - __bfloat162float(h1)));
        }
    }
}

// ---------------------------------------------------------------------------
extern "C" void kernel_launch(void* const* d_in, const int* in_sizes, int n_in,
                              void* d_out, int out_size) {
    const float* x     = (const float*)d_in[0];
    const float* Wq    = (const float*)d_in[1];
    const float* Wk    = (const float*)d_in[2];
    const float* Wv    = (const float*)d_in[3];
    const float* Wo    = (const float*)d_in[4];
    const float* bo    = (const float*)d_in[5];
    const float* gamma = (const float*)d_in[6];
    const float* beta  = (const float*)d_in[7];
    float* out = (float*)d_out;

    ln_kernel<<<RR, 256>>>(x, gamma, beta);
    convw_kernel<<<(4*HH*HH)/256, 256>>>(Wq, Wk, Wv, Wo);

    const int GSMEM = 2*32768;   // two 32 KB stages
    cudaFuncSetAttribute(gemm_mma<0>, cudaFuncAttributeMaxDynamicSharedMemorySize, GSMEM);
    cudaFuncSetAttribute(gemm_mma<3>, cudaFuncAttributeMaxDynamicSharedMemorySize, GSMEM);

    gemm_mma<0><<<dim3(HH/128, RR/128, 3), 256, GSMEM>>>(nullptr, nullptr, nullptr);

    const int ASMEM = 65536;
    cudaFuncSetAttribute(attn_mma, cudaFuncAttributeMaxDynamicSharedMemorySize, ASMEM);
    attn_mma<<<dim3(SS/128, BB*NHH), 256, ASMEM>>>();

    gemm_mma<3><<<dim3(HH/128, RR/128, 1), 256, GSMEM>>>(bo, x, out);
}

// round 13
// speedup vs baseline: 3.8267x; 1.0220x over previous
#include <cuda_runtime.h>
#include <cuda_bf16.h>
#include <cstdint>
#include <math.h>

#define HH   1024
#define NHH  16
#define HDD  64
#define BB   2
#define SS   2048
#define RR   (BB*SS)   // 4096 rows

// ---------------- device scratch (no allocations allowed) -------------------
__device__ __nv_bfloat16 g_qhi[RR*HH], g_qlo[RR*HH];   // [B*NH, S, HD], pre-scaled 0.125
__device__ __nv_bfloat16 g_khi[RR*HH], g_klo[RR*HH];
__device__ __nv_bfloat16 g_vhi[RR*HH], g_vlo[RR*HH];
__device__ __nv_bfloat16 g_xn_hi[RR*HH], g_xn_lo[RR*HH];     // LN output split
__device__ __nv_bfloat16 g_w_hi[4*HH*HH], g_w_lo[4*HH*HH];   // Wq,Wk,Wv,Wo split
__device__ __nv_bfloat16 g_at_hi[RR*HH], g_at_lo[RR*HH];     // attention out split

// ---------------- helpers ---------------------------------------------------
__device__ __forceinline__ uint32_t smem_u32(const void* p) {
    uint32_t a;
    asm("{ .reg .u64 t; cvta.to.shared.u64 t, %1; cvt.u32.u64 %0, t; }" : "=r"(a) : "l"(p));
    return a;
}
#define SWZ(o)   ((o) ^ (((o) >> 3) & 0x70))   // 128B-row swizzle
#define SWZ64(o) ((o) ^ (((o) >> 3) & 0x30))   // 64B-row swizzle

__device__ __forceinline__ void cpasync16(uint32_t dst, const void* src) {
    asm volatile("cp.async.cg.shared.global [%0], [%1], 16;" :: "r"(dst), "l"(src));
}
#define CP_COMMIT() asm volatile("cp.async.commit_group;" ::: "memory")
#define CP_WAIT(n)  asm volatile("cp.async.wait_group %0;" :: "n"(n) : "memory")

__device__ __forceinline__ void ldsm4(uint32_t& r0, uint32_t& r1, uint32_t& r2, uint32_t& r3,
                                      uint32_t a) {
    asm volatile("ldmatrix.sync.aligned.m8n8.x4.shared.b16 {%0,%1,%2,%3}, [%4];"
                 : "=r"(r0), "=r"(r1), "=r"(r2), "=r"(r3) : "r"(a));
}
__device__ __forceinline__ void ldsm4t(uint32_t& r0, uint32_t& r1, uint32_t& r2, uint32_t& r3,
                                       uint32_t a) {
    asm volatile("ldmatrix.sync.aligned.m8n8.x4.trans.shared.b16 {%0,%1,%2,%3}, [%4];"
                 : "=r"(r0), "=r"(r1), "=r"(r2), "=r"(r3) : "r"(a));
}
__device__ __forceinline__ void mma16816(float* c, const uint32_t* a, const uint32_t* b) {
    asm volatile("mma.sync.aligned.m16n8k16.row.col.f32.bf16.bf16.f32 "
                 "{%0,%1,%2,%3}, {%4,%5,%6,%7}, {%8,%9}, {%0,%1,%2,%3};"
                 : "+f"(c[0]), "+f"(c[1]), "+f"(c[2]), "+f"(c[3])
                 : "r"(a[0]), "r"(a[1]), "r"(a[2]), "r"(a[3]), "r"(b[0]), "r"(b[1]));
}
__device__ __forceinline__ uint32_t packbf(float p0, float p1) {
    uint32_t r;
    asm("cvt.rn.bf16x2.f32 %0, %1, %2;" : "=r"(r) : "f"(p1), "f"(p0));
    return r;
}
__device__ __forceinline__ float bfh(float x) {
    return __bfloat162float(__float2bfloat16(x));
}

// ---------------------------------------------------------------------------
// LayerNorm: one block per row, 256 threads, float4 per thread; emits bf16 hi/lo.
// ---------------------------------------------------------------------------
__global__ void ln_kernel(const float* __restrict__ x,
                          const float* __restrict__ gamma,
                          const float* __restrict__ beta) {
    int row = blockIdx.x;
    int t   = threadIdx.x;
    const float4* xr = (const float4*)(x + (size_t)row*HH);
    float4 v = xr[t];
    float s  = v.x + v.y + v.z + v.w;
    float sq = v.x*v.x + v.y*v.y + v.z*v.z + v.w*v.w;

    __shared__ float ssum[8], ssq[8];
    #pragma unroll
    for (int o = 16; o >= 1; o >>= 1) {
        s  += __shfl_xor_sync(0xffffffffu, s,  o);
        sq += __shfl_xor_sync(0xffffffffu, sq, o);
    }
    int warp = t >> 5, lane = t & 31;
    if (lane == 0) { ssum[warp] = s; ssq[warp] = sq; }
    __syncthreads();
    s = 0.f; sq = 0.f;
    #pragma unroll
    for (int i = 0; i < 8; i++) { s += ssum[i]; sq += ssq[i]; }

    float mu  = s * (1.0f/HH);
    float var = sq * (1.0f/HH) - mu*mu;
    float inv = rsqrtf(var + 1e-5f);

    float4 g  = ((const float4*)gamma)[t];
    float4 bt = ((const float4*)beta)[t];
    float o[4];
    o[0] = (v.x-mu)*inv*g.x + bt.x;
    o[1] = (v.y-mu)*inv*g.y + bt.y;
    o[2] = (v.z-mu)*inv*g.z + bt.z;
    o[3] = (v.w-mu)*inv*g.w + bt.w;

    size_t base = (size_t)row*HH + t*4;
    #pragma unroll
    for (int i = 0; i < 4; i++) {
        __nv_bfloat16 h = __float2bfloat16(o[i]);
        g_xn_hi[base+i] = h;
        g_xn_lo[base+i] = __float2bfloat16(o[i] - __bfloat162float(h));
    }
}

// ---------------------------------------------------------------------------
// Weight conversion fp32 -> bf16 hi/lo, all 4 W at once.
// ---------------------------------------------------------------------------
__global__ void convw_kernel(const float* __restrict__ Wq, const float* __restrict__ Wk,
                             const float* __restrict__ Wv, const float* __restrict__ Wo) {
    int i = blockIdx.x*blockDim.x + threadIdx.x;
    const int M = HH*HH;
    const float* src = (i < M) ? Wq : (i < 2*M) ? Wk : (i < 3*M) ? Wv : Wo;
    float x = src[i & (M-1)];
    __nv_bfloat16 h = __float2bfloat16(x);
    g_w_hi[i] = h;
    g_w_lo[i] = __float2bfloat16(x - __bfloat162float(h));
}

// ---------------------------------------------------------------------------
// Split-bf16 HMMA NT-GEMM, 3-stage cp.async ring (prefetch depth 2, ONE barrier
// per chunk). K-chunk 32, stage = 4 tiles (Ahi|Alo|Bhi|Blo) of 128x32 = 32KB.
// 3 stages = 96KB; 2 CTAs/SM (192KB of 228KB). 8 warps (2m x 4n of 64x32).
// MODE 0: dst = q/k/v split bf16 head-layout (q pre-scaled). MODE 3: out+bias+resid.
// ---------------------------------------------------------------------------
template<int MODE>
__global__ __launch_bounds__(256, 2) void gemm_mma(const float* __restrict__ bo,
                                                   const float* __restrict__ resid,
                                                   float* __restrict__ out) {
    extern __shared__ char sm[];
    uint32_t smb = smem_u32(sm);

    int tid = threadIdx.x;
    int w = tid >> 5, lane = tid & 31;
    int wm = w & 1, wn = w >> 1;
    int row0 = blockIdx.y * 128;
    int col0 = blockIdx.x * 128;
    int widx = (MODE == 3) ? 3 : blockIdx.z;

    const __nv_bfloat16* Ahi = (MODE == 3) ? g_at_hi : g_xn_hi;
    const __nv_bfloat16* Alo = (MODE == 3) ? g_at_lo : g_xn_lo;
    const __nv_bfloat16* Bhi = g_w_hi + (size_t)widx*HH*HH;
    const __nv_bfloat16* Blo = g_w_lo + (size_t)widx*HH*HH;

    float acc[4][4][4];
    #pragma unroll
    for (int i = 0; i < 4; i++)
        #pragma unroll
        for (int j = 0; j < 4; j++)
            #pragma unroll
            for (int q = 0; q < 4; q++) acc[i][j][q] = 0.f;

    auto prefetch_chunk = [&](int chunk) {
        int kt = chunk * 32;
        uint32_t stg = smb + (uint32_t)(chunk % 3) * 32768u;
        #pragma unroll
        for (int t = 0; t < 8; t++) {
            int idx = tid + t*256;                // 0..2047 16B slots
            int a   = idx >> 9;                   // 0=Ahi 1=Alo 2=Bhi 3=Blo
            int e   = idx & 511;
            int r   = e >> 2, seg = e & 3;        // 128 rows x 4 segs of 8 bf16
            const __nv_bfloat16* src =
                (a == 0) ? Ahi + (size_t)(row0 + r)*HH + kt :
                (a == 1) ? Alo + (size_t)(row0 + r)*HH + kt :
                (a == 2) ? Bhi + (size_t)(col0 + r)*HH + kt :
                           Blo + (size_t)(col0 + r)*HH + kt;
            cpasync16(stg + (uint32_t)a*8192u + SWZ64((uint32_t)(r*64 + seg*16)),
                      src + seg*8);
        }
        CP_COMMIT();
    };

    prefetch_chunk(0);
    prefetch_chunk(1);

    int a_r  = wm*64 + ((lane >> 3) & 1)*8 + (lane & 7);
    int a_ks = (lane >> 4);
    int b_r  = wn*32 + ((lane >> 4) & 1)*8 + (lane & 7);
    int b_ks = ((lane >> 3) & 1);

    for (int chunk = 0; chunk < 32; ++chunk) {
        if (chunk + 1 < 32) { CP_WAIT(1); } else { CP_WAIT(0); }
        __syncthreads();

        uint32_t st = smb + (uint32_t)(chunk % 3) * 32768u;

        #pragma unroll
        for (int kk = 0; kk < 2; ++kk) {
            int sgA = (kk*2 + a_ks) * 16;
            int sgB = (kk*2 + b_ks) * 16;

            uint32_t Af[4][4], Al[4][4], Bf[4][2], Bl[4][2];
            #pragma unroll
            for (int mf = 0; mf < 4; mf++) {
                uint32_t off = SWZ64((uint32_t)((a_r + mf*16)*64 + sgA));
                ldsm4(Af[mf][0], Af[mf][1], Af[mf][2], Af[mf][3], st + off);
                ldsm4(Al[mf][0], Al[mf][1], Al[mf][2], Al[mf][3], st + 8192u + off);
            }
            #pragma unroll
            for (int nh = 0; nh < 2; nh++) {
                uint32_t off = SWZ64((uint32_t)((b_r + nh*16)*64 + sgB));
                uint32_t r0, r1, r2, r3;
                ldsm4(r0, r1, r2, r3, st + 16384u + off);
                Bf[nh*2+0][0] = r0; Bf[nh*2+0][1] = r1;
                Bf[nh*2+1][0] = r2; Bf[nh*2+1][1] = r3;
                ldsm4(r0, r1, r2, r3, st + 24576u + off);
                Bl[nh*2+0][0] = r0; Bl[nh*2+0][1] = r1;
                Bl[nh*2+1][0] = r2; Bl[nh*2+1][1] = r3;
            }
            #pragma unroll
            for (int mf = 0; mf < 4; mf++)
                #pragma unroll
                for (int nf = 0; nf < 4; nf++) {
                    mma16816(acc[mf][nf], Af[mf], Bf[nf]);
                    mma16816(acc[mf][nf], Af[mf], Bl[nf]);
                    mma16816(acc[mf][nf], Al[mf], Bf[nf]);
                }
        }
        if (chunk + 2 < 32) prefetch_chunk(chunk + 2);
    }

    float qscale = (MODE < 3 && blockIdx.z == 0) ? 0.125f : 1.0f;
    #pragma unroll
    for (int mf = 0; mf < 4; mf++) {
        int mr = row0 + wm*64 + mf*16 + (lane >> 2);
        #pragma unroll
        for (int nf = 0; nf < 4; nf++) {
            int nc = col0 + wn*32 + nf*8 + (lane & 3)*2;
            #pragma unroll
            for (int half = 0; half < 2; half++) {
                int gi = mr + half*8;
                float v0 = acc[mf][nf][half*2 + 0];
                float v1 = acc[mf][nf][half*2 + 1];
                if (MODE < 3) {
                    v0 *= qscale; v1 *= qscale;
                    int b  = gi >> 11;
                    int s_ = gi & 2047;
                    int h  = nc >> 6;
                    int d  = nc & 63;
                    __nv_bfloat16* dhi = (blockIdx.z == 0) ? g_qhi : (blockIdx.z == 1) ? g_khi : g_vhi;
                    __nv_bfloat16* dlo = (blockIdx.z == 0) ? g_qlo : (blockIdx.z == 1) ? g_klo : g_vlo;
                    size_t base = (size_t)(((b << 4) + h)*SS + s_)*HDD + d;
                    __nv_bfloat16 h0 = __float2bfloat16(v0);
                    __nv_bfloat16 h1 = __float2bfloat16(v1);
                    *(__nv_bfloat162*)&dhi[base] = __halves2bfloat162(h0, h1);
                    *(__nv_bfloat162*)&dlo[base] = __halves2bfloat162(
                        __float2bfloat16(v0 - __bfloat162float(h0)),
                        __float2bfloat16(v1 - __bfloat162float(h1)));
                } else {
                    size_t base = (size_t)gi*HH + nc;
                    const float2 rr = *(const float2*)&resid[base];
                    float2* p = (float2*)&out[base];
                    *p = make_float2(v0 + bo[nc] + rr.x, v1 + bo[nc+1] + rr.y);
                }
            }
        }
    }
}

// ---------------------------------------------------------------------------
// HMMA flash attention, 3-stage cp.async ring (prefetch depth 2, ONE barrier
// per K-tile). Block = (bh, 128-query tile), 8 warps x 16 q-rows; 64-key tiles.
// Stage (32KB) = Khi|Klo|Vhi|Vlo, 8KB apiece; 3 stages = 96KB; 2 CTAs/SM.
// Q (128x64 hi/lo, 32KB) staged into stage0 before the pipeline starts.
// ---------------------------------------------------------------------------
__global__ __launch_bounds__(256, 2) void attn_mma() {
    extern __shared__ char sm[];
    uint32_t smb = smem_u32(sm);

    int tid = threadIdx.x;
    int w = tid >> 5, lane = tid & 31;
    int bh = blockIdx.y;
    int qt = blockIdx.x;              // 0..15 (128-query tiles)
    size_t bhoff = (size_t)bh*SS*HDD;

    // ---- stage Q tile (128x64 hi/lo) into stage0, then preload A-fragments ----
    {
        const __nv_bfloat16* Qh = g_qhi + bhoff + (size_t)qt*128*HDD;
        const __nv_bfloat16* Ql = g_qlo + bhoff + (size_t)qt*128*HDD;
        #pragma unroll
        for (int t = 0; t < 8; t++) {
            int idx = tid + t*256;            // 0..2047 uint4 slots
            int a   = idx >> 10;              // 0=hi,1=lo
            int e   = idx & 1023;
            int r   = e >> 3, c16 = e & 7;
            const __nv_bfloat16* src = (a ? Ql : Qh) + (size_t)r*HDD + c16*8;
            cpasync16(smb + (uint32_t)a*16384u + SWZ((uint32_t)(r*128 + c16*16)), src);
        }
        CP_COMMIT();
        CP_WAIT(0);
    }
    __syncthreads();

    uint32_t qh[4][4], ql[4][4];
    {
        int a_r  = w*16 + ((lane >> 3) & 1)*8 + (lane & 7);
        int a_ks = (lane >> 4);
        #pragma unroll
        for (int k16 = 0; k16 < 4; k16++) {
            uint32_t off = SWZ((uint32_t)(a_r*128 + (a_ks + k16*2)*16));
            ldsm4(qh[k16][0], qh[k16][1], qh[k16][2], qh[k16][3], smb + off);
            ldsm4(ql[k16][0], ql[k16][1], ql[k16][2], ql[k16][3], smb + 16384u + off);
        }
    }
    __syncthreads();   // all warps done reading Q before stage0 is overwritten

    const __nv_bfloat16* Kh = g_khi + bhoff;
    const __nv_bfloat16* Kl = g_klo + bhoff;
    const __nv_bfloat16* Vh = g_vhi + bhoff;
    const __nv_bfloat16* Vl = g_vlo + bhoff;

    auto prefetch_tile = [&](int kt) {
        uint32_t stg = smb + (uint32_t)(kt % 3) * 32768u;
        #pragma unroll
        for (int t = 0; t < 8; t++) {
            int idx = tid + t*256;            // 0..2047 uint4 slots
            int a   = idx >> 9;               // 0=Khi 1=Klo 2=Vhi 3=Vlo
            int e   = idx & 511;
            int r   = e >> 3, c16 = e & 7;
            const __nv_bfloat16* src =
                ((a == 0) ? Kh : (a == 1) ? Kl : (a == 2) ? Vh : Vl)
                + (size_t)(kt*64 + r)*HDD + c16*8;
            cpasync16(stg + (uint32_t)a*8192u + SWZ((uint32_t)(r*128 + c16*16)), src);
        }
        CP_COMMIT();
    };

    float m0 = -1e30f, m1 = -1e30f, l0 = 0.f, l1 = 0.f;
    float O[8][4];
    #pragma unroll
    for (int n = 0; n < 8; n++)
        #pragma unroll
        for (int q = 0; q < 4; q++) O[n][q] = 0.f;

    int kb_row = ((lane >> 4) & 1)*8 + (lane & 7);
    int kb_k   = ((lane >> 3) & 1);
    int v_row  = ((lane >> 3) & 1)*8 + (lane & 7);
    int v_col  = ((lane >> 4) & 1)*8;

    prefetch_tile(0);
    prefetch_tile(1);

    const int NT = SS/64;   // 32
    for (int kt = 0; kt < NT; kt++) {
        if (kt + 1 < NT) { CP_WAIT(1); } else { CP_WAIT(0); }
        __syncthreads();

        uint32_t st = smb + (uint32_t)(kt % 3) * 32768u;

        // ---- S = Q K^T (3-term split); per-np fragment loads to cut reg peak ----
        float s[8][4];
        #pragma unroll
        for (int n = 0; n < 8; n++)
            #pragma unroll
            for (int q = 0; q < 4; q++) s[n][q] = 0.f;

        #pragma unroll
        for (int k16 = 0; k16 < 4; k16++) {
            #pragma unroll
            for (int np = 0; np < 4; np++) {
                uint32_t off = SWZ((uint32_t)((np*16 + kb_row)*128 + (kb_k + k16*2)*16));
                uint32_t bh0, bh1, bh2, bh3, bl0, bl1, bl2, bl3;
                ldsm4(bh0, bh1, bh2, bh3, st + off);
                ldsm4(bl0, bl1, bl2, bl3, st + 8192u + off);
                uint32_t bhi[2], bli[2];
                bhi[0] = bh0; bhi[1] = bh1; bli[0] = bl0; bli[1] = bl1;
                mma16816(s[np*2+0], qh[k16], bhi);
                mma16816(s[np*2+0], qh[k16], bli);
                mma16816(s[np*2+0], ql[k16], bhi);
                bhi[0] = bh2; bhi[1] = bh3; bli[0] = bl2; bli[1] = bl3;
                mma16816(s[np*2+1], qh[k16], bhi);
                mma16816(s[np*2+1], qh[k16], bli);
                mma16816(s[np*2+1], ql[k16], bhi);
            }
        }

        // ---- online softmax (rows g=lane>>2 and g+8; quad shuffles) ----
        float mx0 = -1e30f, mx1 = -1e30f;
        #pragma unroll
        for (int n = 0; n < 8; n++) {
            mx0 = fmaxf(mx0, fmaxf(s[n][0], s[n][1]));
            mx1 = fmaxf(mx1, fmaxf(s[n][2], s[n][3]));
        }
        mx0 = fmaxf(mx0, __shfl_xor_sync(0xffffffffu, mx0, 1, 4));
        mx0 = fmaxf(mx0, __shfl_xor_sync(0xffffffffu, mx0, 2, 4));
        mx1 = fmaxf(mx1, __shfl_xor_sync(0xffffffffu, mx1, 1, 4));
        mx1 = fmaxf(mx1, __shfl_xor_sync(0xffffffffu, mx1, 2, 4));
        float m0n = fmaxf(m0, mx0), m1n = fmaxf(m1, mx1);
        float c0 = __expf(m0 - m0n), c1 = __expf(m1 - m1n);
        m0 = m0n; m1 = m1n;

        float rs0 = 0.f, rs1 = 0.f;
        #pragma unroll
        for (int n = 0; n < 8; n++) {
            s[n][0] = __expf(s[n][0] - m0); rs0 += s[n][0];
            s[n][1] = __expf(s[n][1] - m0); rs0 += s[n][1];
            s[n][2] = __expf(s[n][2] - m1); rs1 += s[n][2];
            s[n][3] = __expf(s[n][3] - m1); rs1 += s[n][3];
        }
        rs0 += __shfl_xor_sync(0xffffffffu, rs0, 1, 4);
        rs0 += __shfl_xor_sync(0xffffffffu, rs0, 2, 4);
        rs1 += __shfl_xor_sync(0xffffffffu, rs1, 1, 4);
        rs1 += __shfl_xor_sync(0xffffffffu, rs1, 2, 4);
        l0 = l0*c0 + rs0;
        l1 = l1*c1 + rs1;
        #pragma unroll
        for (int n = 0; n < 8; n++) {
            O[n][0] *= c0; O[n][1] *= c0; O[n][2] *= c1; O[n][3] *= c1;
        }

        // ---- O += P V (3-term split; P from s via C->A fragment identity) ----
        #pragma unroll
        for (int k16 = 0; k16 < 4; k16++) {
            float p00 = s[2*k16][0],   p01 = s[2*k16][1];
            float p02 = s[2*k16][2],   p03 = s[2*k16][3];
            float p10 = s[2*k16+1][0], p11 = s[2*k16+1][1];
            float p12 = s[2*k16+1][2], p13 = s[2*k16+1][3];
            float h00 = bfh(p00), h01 = bfh(p01), h02 = bfh(p02), h03 = bfh(p03);
            float h10 = bfh(p10), h11 = bfh(p11), h12 = bfh(p12), h13 = bfh(p13);
            uint32_t ph[4], pl[4];
            ph[0] = packbf(h00, h01);           ph[1] = packbf(h02, h03);
            ph[2] = packbf(h10, h11);           ph[3] = packbf(h12, h13);
            pl[0] = packbf(p00-h00, p01-h01);   pl[1] = packbf(p02-h02, p03-h03);
            pl[2] = packbf(p10-h10, p11-h11);   pl[3] = packbf(p12-h12, p13-h13);

            #pragma unroll
            for (int np = 0; np < 4; np++) {
                uint32_t off = SWZ((uint32_t)((k16*16 + v_row)*128 + (np*16 + v_col)*2));
                uint32_t vh0, vh1, vh2, vh3, vl0, vl1, vl2, vl3;
                ldsm4t(vh0, vh1, vh2, vh3, st + 16384u + off);
                ldsm4t(vl0, vl1, vl2, vl3, st + 24576u + off);
                uint32_t vhi[2], vli[2];
                vhi[0] = vh0; vhi[1] = vh1; vli[0] = vl0; vli[1] = vl1;
                mma16816(O[np*2+0], ph, vhi);
                mma16816(O[np*2+0], ph, vli);
                mma16816(O[np*2+0], pl, vhi);
                vhi[0] = vh2; vhi[1] = vh3; vli[0] = vl2; vli[1] = vl3;
                mma16816(O[np*2+1], ph, vhi);
                mma16816(O[np*2+1], ph, vli);
                mma16816(O[np*2+1], pl, vhi);
            }
        }
        if (kt + 2 < NT) prefetch_tile(kt + 2);
    }

    // ---- epilogue: O/l -> g_at hi/lo, [B,S,H] with head offset ----
    int b = bh >> 4, h = bh & 15;
    float inv0 = 1.0f / l0, inv1 = 1.0f / l1;
    int gi0 = b*SS + qt*128 + w*16 + (lane >> 2);
    int col = h*64 + (lane & 3)*2;
    #pragma unroll
    for (int n = 0; n < 8; n++) {
        #pragma unroll
        for (int half = 0; half < 2; half++) {
            int gi = gi0 + half*8;
            float v0 = O[n][half*2+0] * (half ? inv1 : inv0);
            float v1 = O[n][half*2+1] * (half ? inv1 : inv0);
            size_t idx = (size_t)gi*HH + col + n*8;
            __nv_bfloat16 h0 = __float2bfloat16(v0);
            __nv_bfloat16 h1 = __float2bfloat16(v1);
            *(__nv_bfloat162*)&g_at_hi[idx] = __halves2bfloat162(h0, h1);
            *(__nv_bfloat162*)&g_at_lo[idx] = __halves2bfloat162(
                __float2bfloat16(v0 - __bfloat162float(h0)),
                __float2bfloat16(v1 - __bfloat162float(h1)));
        }
    }
}

// ---------------------------------------------------------------------------
extern "C" void kernel_launch(void* const* d_in, const int* in_sizes, int n_in,
                              void* d_out, int out_size) {
    const float* x     = (const float*)d_in[0];
    const float* Wq    = (const float*)d_in[1];
    const float* Wk    = (const float*)d_in[2];
    const float* Wv    = (const float*)d_in[3];
    const float* Wo    = (const float*)d_in[4];
    const float* bo    = (const float*)d_in[5];
    const float* gamma = (const float*)d_in[6];
    const float* beta  = (const float*)d_in[7];
    float* out = (float*)d_out;

    ln_kernel<<<RR, 256>>>(x, gamma, beta);
    convw_kernel<<<(4*HH*HH)/256, 256>>>(Wq, Wk, Wv, Wo);

    const int GSMEM = 3*32768;   // three 32 KB stages
    cudaFuncSetAttribute(gemm_mma<0>, cudaFuncAttributeMaxDynamicSharedMemorySize, GSMEM);
    cudaFuncSetAttribute(gemm_mma<3>, cudaFuncAttributeMaxDynamicSharedMemorySize, GSMEM);

    gemm_mma<0><<<dim3(HH/128, RR/128, 3), 256, GSMEM>>>(nullptr, nullptr, nullptr);

    const int ASMEM = 3*32768;
    cudaFuncSetAttribute(attn_mma, cudaFuncAttributeMaxDynamicSharedMemorySize, ASMEM);
    attn_mma<<<dim3(SS/128, BB*NHH), 256, ASMEM>>>();

    gemm_mma<3><<<dim3(HH/128, RR/128, 1), 256, GSMEM>>>(bo, x, out);
}

// round 14
// speedup vs baseline: 5.4883x; 1.4342x over previous
#include <cuda_runtime.h>
#include <cuda_fp16.h>
#include <cstdint>
#include <math.h>

#define HH   1024
#define NHH  16
#define HDD  64
#define BB   2
#define SS   2048
#define RR   (BB*SS)   // 4096 rows

// ---------------- device scratch (no allocations allowed) -------------------
// 2-term fp16 scheme: one operand exact (hi+lo), other truncated (hi only).
__device__ __half g_qh[RR*HH];                 // Q hi only, pre-scaled 0.125
__device__ __half g_kh[RR*HH], g_kl[RR*HH];    // K hi+lo
__device__ __half g_vh[RR*HH], g_vl[RR*HH];    // V hi+lo
__device__ __half g_xn[RR*HH];                 // LN out, hi only (A side of GEMM)
__device__ __half g_wh[4*HH*HH], g_wl[4*HH*HH];// Wq,Wk,Wv,Wo hi+lo (B side)
__device__ __half g_at[RR*HH];                 // attention out, hi only

// ---------------- helpers ---------------------------------------------------
__device__ __forceinline__ uint32_t smem_u32(const void* p) {
    uint32_t a;
    asm("{ .reg .u64 t; cvta.to.shared.u64 t, %1; cvt.u32.u64 %0, t; }" : "=r"(a) : "l"(p));
    return a;
}
#define SWZ(o)   ((o) ^ (((o) >> 3) & 0x70))   // 128B-row swizzle
#define SWZ64(o) ((o) ^ (((o) >> 3) & 0x30))   // 64B-row swizzle

__device__ __forceinline__ void cpasync16(uint32_t dst, const void* src) {
    asm volatile("cp.async.cg.shared.global [%0], [%1], 16;" :: "r"(dst), "l"(src));
}
#define CP_COMMIT() asm volatile("cp.async.commit_group;" ::: "memory")
#define CP_WAIT(n)  asm volatile("cp.async.wait_group %0;" :: "n"(n) : "memory")

__device__ __forceinline__ void ldsm4(uint32_t& r0, uint32_t& r1, uint32_t& r2, uint32_t& r3,
                                      uint32_t a) {
    asm volatile("ldmatrix.sync.aligned.m8n8.x4.shared.b16 {%0,%1,%2,%3}, [%4];"
                 : "=r"(r0), "=r"(r1), "=r"(r2), "=r"(r3) : "r"(a));
}
__device__ __forceinline__ void ldsm4t(uint32_t& r0, uint32_t& r1, uint32_t& r2, uint32_t& r3,
                                       uint32_t a) {
    asm volatile("ldmatrix.sync.aligned.m8n8.x4.trans.shared.b16 {%0,%1,%2,%3}, [%4];"
                 : "=r"(r0), "=r"(r1), "=r"(r2), "=r"(r3) : "r"(a));
}
__device__ __forceinline__ void mma16816(float* c, const uint32_t* a, const uint32_t* b) {
    asm volatile("mma.sync.aligned.m16n8k16.row.col.f32.f16.f16.f32 "
                 "{%0,%1,%2,%3}, {%4,%5,%6,%7}, {%8,%9}, {%0,%1,%2,%3};"
                 : "+f"(c[0]), "+f"(c[1]), "+f"(c[2]), "+f"(c[3])
                 : "r"(a[0]), "r"(a[1]), "r"(a[2]), "r"(a[3]), "r"(b[0]), "r"(b[1]));
}
__device__ __forceinline__ uint32_t packh(float p0, float p1) {   // p0 -> low half
    __half2 h = __floats2half2_rn(p0, p1);
    return *reinterpret_cast<uint32_t*>(&h);
}

// ---------------------------------------------------------------------------
// LayerNorm: one block per row, 256 threads, float4 per thread; emits fp16 hi.
// ---------------------------------------------------------------------------
__global__ void ln_kernel(const float* __restrict__ x,
                          const float* __restrict__ gamma,
                          const float* __restrict__ beta) {
    int row = blockIdx.x;
    int t   = threadIdx.x;
    const float4* xr = (const float4*)(x + (size_t)row*HH);
    float4 v = xr[t];
    float s  = v.x + v.y + v.z + v.w;
    float sq = v.x*v.x + v.y*v.y + v.z*v.z + v.w*v.w;

    __shared__ float ssum[8], ssq[8];
    #pragma unroll
    for (int o = 16; o >= 1; o >>= 1) {
        s  += __shfl_xor_sync(0xffffffffu, s,  o);
        sq += __shfl_xor_sync(0xffffffffu, sq, o);
    }
    int warp = t >> 5, lane = t & 31;
    if (lane == 0) { ssum[warp] = s; ssq[warp] = sq; }
    __syncthreads();
    s = 0.f; sq = 0.f;
    #pragma unroll
    for (int i = 0; i < 8; i++) { s += ssum[i]; sq += ssq[i]; }

    float mu  = s * (1.0f/HH);
    float var = sq * (1.0f/HH) - mu*mu;
    float inv = rsqrtf(var + 1e-5f);

    float4 g  = ((const float4*)gamma)[t];
    float4 bt = ((const float4*)beta)[t];
    float o[4];
    o[0] = (v.x-mu)*inv*g.x + bt.x;
    o[1] = (v.y-mu)*inv*g.y + bt.y;
    o[2] = (v.z-mu)*inv*g.z + bt.z;
    o[3] = (v.w-mu)*inv*g.w + bt.w;

    size_t base = (size_t)row*HH + t*4;
    #pragma unroll
    for (int i = 0; i < 4; i++)
        g_xn[base+i] = __float2half(o[i]);
}

// ---------------------------------------------------------------------------
// Weight conversion fp32 -> fp16 hi/lo, all 4 W at once.
// ---------------------------------------------------------------------------
__global__ void convw_kernel(const float* __restrict__ Wq, const float* __restrict__ Wk,
                             const float* __restrict__ Wv, const float* __restrict__ Wo) {
    int i = blockIdx.x*blockDim.x + threadIdx.x;
    const int M = HH*HH;
    const float* src = (i < M) ? Wq : (i < 2*M) ? Wk : (i < 3*M) ? Wv : Wo;
    float x = src[i & (M-1)];
    __half h = __float2half(x);
    g_wh[i] = h;
    g_wl[i] = __float2half(x - __half2float(h));
}

// ---------------------------------------------------------------------------
// 2-term fp16 HMMA NT-GEMM: C = Ahi * (Whi + Wlo).
// 3-stage cp.async ring, K-chunk 32. Stage = Ah(8K)|Wh(8K)|Wl(8K) = 24KB.
// 8 warps (2m x 4n of 64x32), 2 CTAs/SM.
// MODE 0: dst = q/k/v fp16 head-layout (q pre-scaled). MODE 3: out+bias+resid.
// ---------------------------------------------------------------------------
template<int MODE>
__global__ __launch_bounds__(256, 2) void gemm_mma(const float* __restrict__ bo,
                                                   const float* __restrict__ resid,
                                                   float* __restrict__ out) {
    extern __shared__ char sm[];
    uint32_t smb = smem_u32(sm);

    int tid = threadIdx.x;
    int w = tid >> 5, lane = tid & 31;
    int wm = w & 1, wn = w >> 1;
    int row0 = blockIdx.y * 128;
    int col0 = blockIdx.x * 128;
    int widx = (MODE == 3) ? 3 : blockIdx.z;

    const __half* A  = (MODE == 3) ? g_at : g_xn;
    const __half* Wh = g_wh + (size_t)widx*HH*HH;
    const __half* Wl = g_wl + (size_t)widx*HH*HH;

    float acc[4][4][4];
    #pragma unroll
    for (int i = 0; i < 4; i++)
        #pragma unroll
        for (int j = 0; j < 4; j++)
            #pragma unroll
            for (int q = 0; q < 4; q++) acc[i][j][q] = 0.f;

    auto prefetch_chunk = [&](int chunk) {
        int kt = chunk * 32;
        uint32_t stg = smb + (uint32_t)(chunk % 3) * 24576u;
        #pragma unroll
        for (int t = 0; t < 6; t++) {
            int idx = tid + t*256;                // 0..1535 16B slots
            int a   = idx >> 9;                   // 0=A 1=Wh 2=Wl
            int e   = idx & 511;
            int r   = e >> 2, seg = e & 3;        // 128 rows x 4 segs of 8 halves
            const __half* src =
                (a == 0) ? A  + (size_t)(row0 + r)*HH + kt :
                (a == 1) ? Wh + (size_t)(col0 + r)*HH + kt :
                           Wl + (size_t)(col0 + r)*HH + kt;
            cpasync16(stg + (uint32_t)a*8192u + SWZ64((uint32_t)(r*64 + seg*16)),
                      src + seg*8);
        }
        CP_COMMIT();
    };

    prefetch_chunk(0);
    prefetch_chunk(1);

    int a_r  = wm*64 + ((lane >> 3) & 1)*8 + (lane & 7);
    int a_ks = (lane >> 4);
    int b_r  = wn*32 + ((lane >> 4) & 1)*8 + (lane & 7);
    int b_ks = ((lane >> 3) & 1);

    for (int chunk = 0; chunk < 32; ++chunk) {
        if (chunk + 1 < 32) { CP_WAIT(1); } else { CP_WAIT(0); }
        __syncthreads();

        uint32_t st = smb + (uint32_t)(chunk % 3) * 24576u;

        #pragma unroll
        for (int kk = 0; kk < 2; ++kk) {
            int sgA = (kk*2 + a_ks) * 16;
            int sgB = (kk*2 + b_ks) * 16;

            uint32_t Af[4][4], Bf[4][2], Bl[4][2];
            #pragma unroll
            for (int mf = 0; mf < 4; mf++) {
                uint32_t off = SWZ64((uint32_t)((a_r + mf*16)*64 + sgA));
                ldsm4(Af[mf][0], Af[mf][1], Af[mf][2], Af[mf][3], st + off);
            }
            #pragma unroll
            for (int nh = 0; nh < 2; nh++) {
                uint32_t off = SWZ64((uint32_t)((b_r + nh*16)*64 + sgB));
                uint32_t r0, r1, r2, r3;
                ldsm4(r0, r1, r2, r3, st + 8192u + off);
                Bf[nh*2+0][0] = r0; Bf[nh*2+0][1] = r1;
                Bf[nh*2+1][0] = r2; Bf[nh*2+1][1] = r3;
                ldsm4(r0, r1, r2, r3, st + 16384u + off);
                Bl[nh*2+0][0] = r0; Bl[nh*2+0][1] = r1;
                Bl[nh*2+1][0] = r2; Bl[nh*2+1][1] = r3;
            }
            #pragma unroll
            for (int mf = 0; mf < 4; mf++)
                #pragma unroll
                for (int nf = 0; nf < 4; nf++) {
                    mma16816(acc[mf][nf], Af[mf], Bf[nf]);
                    mma16816(acc[mf][nf], Af[mf], Bl[nf]);
                }
        }
        if (chunk + 2 < 32) prefetch_chunk(chunk + 2);
    }

    float qscale = (MODE < 3 && blockIdx.z == 0) ? 0.125f : 1.0f;
    #pragma unroll
    for (int mf = 0; mf < 4; mf++) {
        int mr = row0 + wm*64 + mf*16 + (lane >> 2);
        #pragma unroll
        for (int nf = 0; nf < 4; nf++) {
            int nc = col0 + wn*32 + nf*8 + (lane & 3)*2;
            #pragma unroll
            for (int half = 0; half < 2; half++) {
                int gi = mr + half*8;
                float v0 = acc[mf][nf][half*2 + 0];
                float v1 = acc[mf][nf][half*2 + 1];
                if (MODE < 3) {
                    v0 *= qscale; v1 *= qscale;
                    int b  = gi >> 11;
                    int s_ = gi & 2047;
                    int h  = nc >> 6;
                    int d  = nc & 63;
                    size_t base = (size_t)(((b << 4) + h)*SS + s_)*HDD + d;
                    __half h0 = __float2half(v0);
                    __half h1 = __float2half(v1);
                    if (blockIdx.z == 0) {
                        *(__half2*)&g_qh[base] = __halves2half2(h0, h1);
                    } else {
                        __half* dh = (blockIdx.z == 1) ? g_kh : g_vh;
                        __half* dl = (blockIdx.z == 1) ? g_kl : g_vl;
                        *(__half2*)&dh[base] = __halves2half2(h0, h1);
                        *(__half2*)&dl[base] = __halves2half2(
                            __float2half(v0 - __half2float(h0)),
                            __float2half(v1 - __half2float(h1)));
                    }
                } else {
                    size_t base = (size_t)gi*HH + nc;
                    const float2 rr = *(const float2*)&resid[base];
                    float2* p = (float2*)&out[base];
                    *p = make_float2(v0 + bo[nc] + rr.x, v1 + bo[nc+1] + rr.y);
                }
            }
        }
    }
}

// ---------------------------------------------------------------------------
// 2-term fp16 HMMA flash attention: S = qh*(kh+kl), O = ph*(vh+vl).
// 3-stage cp.async ring, one barrier per K-tile. Block = (bh, 128 queries),
// 8 warps x 16 q-rows; 64-key tiles. Stage (32KB) = Kh|Kl|Vh|Vl, 8KB apiece.
// Q (128x64 fp16 hi, 16KB) staged into stage0 before the pipeline starts.
// ---------------------------------------------------------------------------
__global__ __launch_bounds__(256, 2) void attn_mma() {
    extern __shared__ char sm[];
    uint32_t smb = smem_u32(sm);

    int tid = threadIdx.x;
    int w = tid >> 5, lane = tid & 31;
    int bh = blockIdx.y;
    int qt = blockIdx.x;              // 0..15 (128-query tiles)
    size_t bhoff = (size_t)bh*SS*HDD;

    // ---- stage Q tile (128x64 hi) into stage0, then preload A-fragments ----
    {
        const __half* Qh = g_qh + bhoff + (size_t)qt*128*HDD;
        #pragma unroll
        for (int t = 0; t < 4; t++) {
            int idx = tid + t*256;            // 0..1023 uint4 slots
            int r   = idx >> 3, c16 = idx & 7;
            cpasync16(smb + SWZ((uint32_t)(r*128 + c16*16)), Qh + (size_t)r*HDD + c16*8);
        }
        CP_COMMIT();
        CP_WAIT(0);
    }
    __syncthreads();

    uint32_t qh[4][4];
    {
        int a_r  = w*16 + ((lane >> 3) & 1)*8 + (lane & 7);
        int a_ks = (lane >> 4);
        #pragma unroll
        for (int k16 = 0; k16 < 4; k16++) {
            uint32_t off = SWZ((uint32_t)(a_r*128 + (a_ks + k16*2)*16));
            ldsm4(qh[k16][0], qh[k16][1], qh[k16][2], qh[k16][3], smb + off);
        }
    }
    __syncthreads();   // all warps done reading Q before stage0 is overwritten

    const __half* Kh = g_kh + bhoff;
    const __half* Kl = g_kl + bhoff;
    const __half* Vh = g_vh + bhoff;
    const __half* Vl = g_vl + bhoff;

    auto prefetch_tile = [&](int kt) {
        uint32_t stg = smb + (uint32_t)(kt % 3) * 32768u;
        #pragma unroll
        for (int t = 0; t < 8; t++) {
            int idx = tid + t*256;            // 0..2047 uint4 slots
            int a   = idx >> 9;               // 0=Kh 1=Kl 2=Vh 3=Vl
            int e   = idx & 511;
            int r   = e >> 3, c16 = e & 7;
            const __half* src =
                ((a == 0) ? Kh : (a == 1) ? Kl : (a == 2) ? Vh : Vl)
                + (size_t)(kt*64 + r)*HDD + c16*8;
            cpasync16(stg + (uint32_t)a*8192u + SWZ((uint32_t)(r*128 + c16*16)), src);
        }
        CP_COMMIT();
    };

    float m0 = -1e30f, m1 = -1e30f, l0 = 0.f, l1 = 0.f;
    float O[8][4];
    #pragma unroll
    for (int n = 0; n < 8; n++)
        #pragma unroll
        for (int q = 0; q < 4; q++) O[n][q] = 0.f;

    int kb_row = ((lane >> 4) & 1)*8 + (lane & 7);
    int kb_k   = ((lane >> 3) & 1);
    int v_row  = ((lane >> 3) & 1)*8 + (lane & 7);
    int v_col  = ((lane >> 4) & 1)*8;

    prefetch_tile(0);
    prefetch_tile(1);

    const int NT = SS/64;   // 32
    for (int kt = 0; kt < NT; kt++) {
        if (kt + 1 < NT) { CP_WAIT(1); } else { CP_WAIT(0); }
        __syncthreads();

        uint32_t st = smb + (uint32_t)(kt % 3) * 32768u;

        // ---- S = qh * (kh + kl) ----
        float s[8][4];
        #pragma unroll
        for (int n = 0; n < 8; n++)
            #pragma unroll
            for (int q = 0; q < 4; q++) s[n][q] = 0.f;

        #pragma unroll
        for (int k16 = 0; k16 < 4; k16++) {
            #pragma unroll
            for (int np = 0; np < 4; np++) {
                uint32_t off = SWZ((uint32_t)((np*16 + kb_row)*128 + (kb_k + k16*2)*16));
                uint32_t h0, h1, h2, h3, e0, e1, e2, e3;
                ldsm4(h0, h1, h2, h3, st + off);
                ldsm4(e0, e1, e2, e3, st + 8192u + off);
                uint32_t bhi[2], bli[2];
                bhi[0] = h0; bhi[1] = h1; bli[0] = e0; bli[1] = e1;
                mma16816(s[np*2+0], qh[k16], bhi);
                mma16816(s[np*2+0], qh[k16], bli);
                bhi[0] = h2; bhi[1] = h3; bli[0] = e2; bli[1] = e3;
                mma16816(s[np*2+1], qh[k16], bhi);
                mma16816(s[np*2+1], qh[k16], bli);
            }
        }

        // ---- online softmax (rows g=lane>>2 and g+8; quad shuffles) ----
        float mx0 = -1e30f, mx1 = -1e30f;
        #pragma unroll
        for (int n = 0; n < 8; n++) {
            mx0 = fmaxf(mx0, fmaxf(s[n][0], s[n][1]));
            mx1 = fmaxf(mx1, fmaxf(s[n][2], s[n][3]));
        }
        mx0 = fmaxf(mx0, __shfl_xor_sync(0xffffffffu, mx0, 1, 4));
        mx0 = fmaxf(mx0, __shfl_xor_sync(0xffffffffu, mx0, 2, 4));
        mx1 = fmaxf(mx1, __shfl_xor_sync(0xffffffffu, mx1, 1, 4));
        mx1 = fmaxf(mx1, __shfl_xor_sync(0xffffffffu, mx1, 2, 4));
        float m0n = fmaxf(m0, mx0), m1n = fmaxf(m1, mx1);
        float c0 = __expf(m0 - m0n), c1 = __expf(m1 - m1n);
        m0 = m0n; m1 = m1n;

        float rs0 = 0.f, rs1 = 0.f;
        #pragma unroll
        for (int n = 0; n < 8; n++) {
            s[n][0] = __expf(s[n][0] - m0); rs0 += s[n][0];
            s[n][1] = __expf(s[n][1] - m0); rs0 += s[n][1];
            s[n][2] = __expf(s[n][2] - m1); rs1 += s[n][2];
            s[n][3] = __expf(s[n][3] - m1); rs1 += s[n][3];
        }
        rs0 += __shfl_xor_sync(0xffffffffu, rs0, 1, 4);
        rs0 += __shfl_xor_sync(0xffffffffu, rs0, 2, 4);
        rs1 += __shfl_xor_sync(0xffffffffu, rs1, 1, 4);
        rs1 += __shfl_xor_sync(0xffffffffu, rs1, 2, 4);
        l0 = l0*c0 + rs0;
        l1 = l1*c1 + rs1;
        #pragma unroll
        for (int n = 0; n < 8; n++) {
            O[n][0] *= c0; O[n][1] *= c0; O[n][2] *= c1; O[n][3] *= c1;
        }

        // ---- O += ph * (vh + vl); P truncated to fp16 (A operand) ----
        #pragma unroll
        for (int k16 = 0; k16 < 4; k16++) {
            uint32_t ph[4];
            ph[0] = packh(s[2*k16][0],   s[2*k16][1]);
            ph[1] = packh(s[2*k16][2],   s[2*k16][3]);
            ph[2] = packh(s[2*k16+1][0], s[2*k16+1][1]);
            ph[3] = packh(s[2*k16+1][2], s[2*k16+1][3]);

            #pragma unroll
            for (int np = 0; np < 4; np++) {
                uint32_t off = SWZ((uint32_t)((k16*16 + v_row)*128 + (np*16 + v_col)*2));
                uint32_t h0, h1, h2, h3, e0, e1, e2, e3;
                ldsm4t(h0, h1, h2, h3, st + 16384u + off);
                ldsm4t(e0, e1, e2, e3, st + 24576u + off);
                uint32_t vhi[2], vli[2];
                vhi[0] = h0; vhi[1] = h1; vli[0] = e0; vli[1] = e1;
                mma16816(O[np*2+0], ph, vhi);
                mma16816(O[np*2+0], ph, vli);
                vhi[0] = h2; vhi[1] = h3; vli[0] = e2; vli[1] = e3;
                mma16816(O[np*2+1], ph, vhi);
                mma16816(O[np*2+1], ph, vli);
            }
        }
        if (kt + 2 < NT) prefetch_tile(kt + 2);
    }

    // ---- epilogue: O/l -> g_at (fp16 hi), [B,S,H] with head offset ----
    int b = bh >> 4, h = bh & 15;
    float inv0 = 1.0f / l0, inv1 = 1.0f / l1;
    int gi0 = b*SS + qt*128 + w*16 + (lane >> 2);
    int col = h*64 + (lane & 3)*2;
    #pragma unroll
    for (int n = 0; n < 8; n++) {
        #pragma unroll
        for (int half = 0; half < 2; half++) {
            int gi = gi0 + half*8;
            float v0 = O[n][half*2+0] * (half ? inv1 : inv0);
            float v1 = O[n][half*2+1] * (half ? inv1 : inv0);
            size_t idx = (size_t)gi*HH + col + n*8;
            *(__half2*)&g_at[idx] = __floats2half2_rn(v0, v1);
        }
    }
}

// ---------------------------------------------------------------------------
extern "C" void kernel_launch(void* const* d_in, const int* in_sizes, int n_in,
                              void* d_out, int out_size) {
    const float* x     = (const float*)d_in[0];
    const float* Wq    = (const float*)d_in[1];
    const float* Wk    = (const float*)d_in[2];
    const float* Wv    = (const float*)d_in[3];
    const float* Wo    = (const float*)d_in[4];
    const float* bo    = (const float*)d_in[5];
    const float* gamma = (const float*)d_in[6];
    const float* beta  = (const float*)d_in[7];
    float* out = (float*)d_out;

    ln_kernel<<<RR, 256>>>(x, gamma, beta);
    convw_kernel<<<(4*HH*HH)/256, 256>>>(Wq, Wk, Wv, Wo);

    const int GSMEM = 3*24576;   // three 24 KB stages
    cudaFuncSetAttribute(gemm_mma<0>, cudaFuncAttributeMaxDynamicSharedMemorySize, GSMEM);
    cudaFuncSetAttribute(gemm_mma<3>, cudaFuncAttributeMaxDynamicSharedMemorySize, GSMEM);

    gemm_mma<0><<<dim3(HH/128, RR/128, 3), 256, GSMEM>>>(nullptr, nullptr, nullptr);

    const int ASMEM = 3*32768;
    cudaFuncSetAttribute(attn_mma, cudaFuncAttributeMaxDynamicSharedMemorySize, ASMEM);
    attn_mma<<<dim3(SS/128, BB*NHH), 256, ASMEM>>>();

    gemm_mma<3><<<dim3(HH/128, RR/128, 1), 256, GSMEM>>>(bo, x, out);
}

// round 15
// speedup vs baseline: 8.5925x; 1.5656x over previous
#include <cuda_runtime.h>
#include <cuda_fp16.h>
#include <cstdint>
#include <math.h>

#define HH   1024
#define NHH  16
#define HDD  64
#define BB   2
#define SS   2048
#define RR   (BB*SS)   // 4096 rows

// ---------------- device scratch (no allocations allowed) -------------------
__device__ __half g_qh[RR*HH];     // [B*NH, S, HD] fp16, pre-scaled 0.125
__device__ __half g_kh[RR*HH];
__device__ __half g_vh[RR*HH];
__device__ __half g_xn[RR*HH];     // LN out fp16
__device__ __half g_wh[4*HH*HH];   // Wq,Wk,Wv,Wo fp16
__device__ __half g_at[RR*HH];     // attention out fp16

// ---------------- helpers ---------------------------------------------------
__device__ __forceinline__ uint32_t smem_u32(const void* p) {
    uint32_t a;
    asm("{ .reg .u64 t; cvta.to.shared.u64 t, %1; cvt.u32.u64 %0, t; }" : "=r"(a) : "l"(p));
    return a;
}
#define SWZ(o)   ((o) ^ (((o) >> 3) & 0x70))   // 128B-row swizzle
#define SWZ64(o) ((o) ^ (((o) >> 3) & 0x30))   // 64B-row swizzle

__device__ __forceinline__ void cpasync16(uint32_t dst, const void* src) {
    asm volatile("cp.async.cg.shared.global [%0], [%1], 16;" :: "r"(dst), "l"(src));
}
#define CP_COMMIT() asm volatile("cp.async.commit_group;" ::: "memory")
#define CP_WAIT(n)  asm volatile("cp.async.wait_group %0;" :: "n"(n) : "memory")

__device__ __forceinline__ void ldsm4(uint32_t& r0, uint32_t& r1, uint32_t& r2, uint32_t& r3,
                                      uint32_t a) {
    asm volatile("ldmatrix.sync.aligned.m8n8.x4.shared.b16 {%0,%1,%2,%3}, [%4];"
                 : "=r"(r0), "=r"(r1), "=r"(r2), "=r"(r3) : "r"(a));
}
__device__ __forceinline__ void ldsm4t(uint32_t& r0, uint32_t& r1, uint32_t& r2, uint32_t& r3,
                                       uint32_t a) {
    asm volatile("ldmatrix.sync.aligned.m8n8.x4.trans.shared.b16 {%0,%1,%2,%3}, [%4];"
                 : "=r"(r0), "=r"(r1), "=r"(r2), "=r"(r3) : "r"(a));
}
__device__ __forceinline__ void mma16816(float* c, const uint32_t* a, const uint32_t* b) {
    asm volatile("mma.sync.aligned.m16n8k16.row.col.f32.f16.f16.f32 "
                 "{%0,%1,%2,%3}, {%4,%5,%6,%7}, {%8,%9}, {%0,%1,%2,%3};"
                 : "+f"(c[0]), "+f"(c[1]), "+f"(c[2]), "+f"(c[3])
                 : "r"(a[0]), "r"(a[1]), "r"(a[2]), "r"(a[3]), "r"(b[0]), "r"(b[1]));
}
__device__ __forceinline__ uint32_t packh(float p0, float p1) {   // p0 -> low half
    __half2 h = __floats2half2_rn(p0, p1);
    return *reinterpret_cast<uint32_t*>(&h);
}

// ---------------------------------------------------------------------------
// LayerNorm: one block per row, 256 threads, float4 per thread; emits fp16.
// ---------------------------------------------------------------------------
__global__ void ln_kernel(const float* __restrict__ x,
                          const float* __restrict__ gamma,
                          const float* __restrict__ beta) {
    int row = blockIdx.x;
    int t   = threadIdx.x;
    const float4* xr = (const float4*)(x + (size_t)row*HH);
    float4 v = xr[t];
    float s  = v.x + v.y + v.z + v.w;
    float sq = v.x*v.x + v.y*v.y + v.z*v.z + v.w*v.w;

    __shared__ float ssum[8], ssq[8];
    #pragma unroll
    for (int o = 16; o >= 1; o >>= 1) {
        s  += __shfl_xor_sync(0xffffffffu, s,  o);
        sq += __shfl_xor_sync(0xffffffffu, sq, o);
    }
    int warp = t >> 5, lane = t & 31;
    if (lane == 0) { ssum[warp] = s; ssq[warp] = sq; }
    __syncthreads();
    s = 0.f; sq = 0.f;
    #pragma unroll
    for (int i = 0; i < 8; i++) { s += ssum[i]; sq += ssq[i]; }

    float mu  = s * (1.0f/HH);
    float var = sq * (1.0f/HH) - mu*mu;
    float inv = rsqrtf(var + 1e-5f);

    float4 g  = ((const float4*)gamma)[t];
    float4 bt = ((const float4*)beta)[t];
    size_t base = (size_t)row*HH + t*4;
    g_xn[base+0] = __float2half((v.x-mu)*inv*g.x + bt.x);
    g_xn[base+1] = __float2half((v.y-mu)*inv*g.y + bt.y);
    g_xn[base+2] = __float2half((v.z-mu)*inv*g.z + bt.z);
    g_xn[base+3] = __float2half((v.w-mu)*inv*g.w + bt.w);
}

// ---------------------------------------------------------------------------
// Weight conversion fp32 -> fp16, all 4 W at once.
// ---------------------------------------------------------------------------
__global__ void convw_kernel(const float* __restrict__ Wq, const float* __restrict__ Wk,
                             const float* __restrict__ Wv, const float* __restrict__ Wo) {
    int i = blockIdx.x*blockDim.x + threadIdx.x;
    const int M = HH*HH;
    const float* src = (i < M) ? Wq : (i < 2*M) ? Wk : (i < 3*M) ? Wv : Wo;
    g_wh[i] = __float2half(src[i & (M-1)]);
}

// ---------------------------------------------------------------------------
// fp16 HMMA NT-GEMM: C = A * W^T. 3-stage cp.async ring, K-chunk 32.
// Stage = A(8K)|W(8K) = 16KB; 3 stages = 48KB; 2 CTAs/SM.
// 8 warps (2m x 4n of 64x32).
// MODE 0: dst = q/k/v fp16 head-layout (q pre-scaled). MODE 3: out+bias+resid.
// ---------------------------------------------------------------------------
template<int MODE>
__global__ __launch_bounds__(256, 2) void gemm_mma(const float* __restrict__ bo,
                                                   const float* __restrict__ resid,
                                                   float* __restrict__ out) {
    extern __shared__ char sm[];
    uint32_t smb = smem_u32(sm);

    int tid = threadIdx.x;
    int w = tid >> 5, lane = tid & 31;
    int wm = w & 1, wn = w >> 1;
    int row0 = blockIdx.y * 128;
    int col0 = blockIdx.x * 128;
    int widx = (MODE == 3) ? 3 : blockIdx.z;

    const __half* A  = (MODE == 3) ? g_at : g_xn;
    const __half* Wh = g_wh + (size_t)widx*HH*HH;

    float acc[4][4][4];
    #pragma unroll
    for (int i = 0; i < 4; i++)
        #pragma unroll
        for (int j = 0; j < 4; j++)
            #pragma unroll
            for (int q = 0; q < 4; q++) acc[i][j][q] = 0.f;

    auto prefetch_chunk = [&](int chunk) {
        int kt = chunk * 32;
        uint32_t stg = smb + (uint32_t)(chunk % 3) * 16384u;
        #pragma unroll
        for (int t = 0; t < 4; t++) {
            int idx = tid + t*256;                // 0..1023 16B slots
            int a   = idx >> 9;                   // 0=A 1=W
            int e   = idx & 511;
            int r   = e >> 2, seg = e & 3;        // 128 rows x 4 segs of 8 halves
            const __half* src =
                (a == 0) ? A  + (size_t)(row0 + r)*HH + kt :
                           Wh + (size_t)(col0 + r)*HH + kt;
            cpasync16(stg + (uint32_t)a*8192u + SWZ64((uint32_t)(r*64 + seg*16)),
                      src + seg*8);
        }
        CP_COMMIT();
    };

    prefetch_chunk(0);
    prefetch_chunk(1);

    int a_r  = wm*64 + ((lane >> 3) & 1)*8 + (lane & 7);
    int a_ks = (lane >> 4);
    int b_r  = wn*32 + ((lane >> 4) & 1)*8 + (lane & 7);
    int b_ks = ((lane >> 3) & 1);

    for (int chunk = 0; chunk < 32; ++chunk) {
        if (chunk + 1 < 32) { CP_WAIT(1); } else { CP_WAIT(0); }
        __syncthreads();

        uint32_t st = smb + (uint32_t)(chunk % 3) * 16384u;

        #pragma unroll
        for (int kk = 0; kk < 2; ++kk) {
            int sgA = (kk*2 + a_ks) * 16;
            int sgB = (kk*2 + b_ks) * 16;

            uint32_t Af[4][4], Bf[4][2];
            #pragma unroll
            for (int mf = 0; mf < 4; mf++) {
                uint32_t off = SWZ64((uint32_t)((a_r + mf*16)*64 + sgA));
                ldsm4(Af[mf][0], Af[mf][1], Af[mf][2], Af[mf][3], st + off);
            }
            #pragma unroll
            for (int nh = 0; nh < 2; nh++) {
                uint32_t off = SWZ64((uint32_t)((b_r + nh*16)*64 + sgB));
                uint32_t r0, r1, r2, r3;
                ldsm4(r0, r1, r2, r3, st + 8192u + off);
                Bf[nh*2+0][0] = r0; Bf[nh*2+0][1] = r1;
                Bf[nh*2+1][0] = r2; Bf[nh*2+1][1] = r3;
            }
            #pragma unroll
            for (int mf = 0; mf < 4; mf++)
                #pragma unroll
                for (int nf = 0; nf < 4; nf++)
                    mma16816(acc[mf][nf], Af[mf], Bf[nf]);
        }
        if (chunk + 2 < 32) prefetch_chunk(chunk + 2);
    }

    float qscale = (MODE < 3 && blockIdx.z == 0) ? 0.125f : 1.0f;
    #pragma unroll
    for (int mf = 0; mf < 4; mf++) {
        int mr = row0 + wm*64 + mf*16 + (lane >> 2);
        #pragma unroll
        for (int nf = 0; nf < 4; nf++) {
            int nc = col0 + wn*32 + nf*8 + (lane & 3)*2;
            #pragma unroll
            for (int half = 0; half < 2; half++) {
                int gi = mr + half*8;
                float v0 = acc[mf][nf][half*2 + 0];
                float v1 = acc[mf][nf][half*2 + 1];
                if (MODE < 3) {
                    v0 *= qscale; v1 *= qscale;
                    int b  = gi >> 11;
                    int s_ = gi & 2047;
                    int h  = nc >> 6;
                    int d  = nc & 63;
                    __half* dh = (blockIdx.z == 0) ? g_qh : (blockIdx.z == 1) ? g_kh : g_vh;
                    size_t base = (size_t)(((b << 4) + h)*SS + s_)*HDD + d;
                    *(__half2*)&dh[base] = __floats2half2_rn(v0, v1);
                } else {
                    size_t base = (size_t)gi*HH + nc;
                    const float2 rr = *(const float2*)&resid[base];
                    float2* p = (float2*)&out[base];
                    *p = make_float2(v0 + bo[nc] + rr.x, v1 + bo[nc+1] + rr.y);
                }
            }
        }
    }
}

// ---------------------------------------------------------------------------
// fp16 HMMA flash attention: S = qh*kh, O = ph*vh.
// 3-stage cp.async ring, one barrier per K-tile. Block = (bh, 128 queries),
// 8 warps x 16 q-rows; 64-key tiles. Stage (16KB) = Kh|Vh, 8KB apiece.
// Q (128x64 fp16, 16KB) staged into stage0 before the pipeline starts.
// ---------------------------------------------------------------------------
__global__ __launch_bounds__(256, 2) void attn_mma() {
    extern __shared__ char sm[];
    uint32_t smb = smem_u32(sm);

    int tid = threadIdx.x;
    int w = tid >> 5, lane = tid & 31;
    int bh = blockIdx.y;
    int qt = blockIdx.x;              // 0..15 (128-query tiles)
    size_t bhoff = (size_t)bh*SS*HDD;

    // ---- stage Q tile (128x64) into stage0, then preload A-fragments ----
    {
        const __half* Qh = g_qh + bhoff + (size_t)qt*128*HDD;
        #pragma unroll
        for (int t = 0; t < 4; t++) {
            int idx = tid + t*256;            // 0..1023 uint4 slots
            int r   = idx >> 3, c16 = idx & 7;
            cpasync16(smb + SWZ((uint32_t)(r*128 + c16*16)), Qh + (size_t)r*HDD + c16*8);
        }
        CP_COMMIT();
        CP_WAIT(0);
    }
    __syncthreads();

    uint32_t qh[4][4];
    {
        int a_r  = w*16 + ((lane >> 3) & 1)*8 + (lane & 7);
        int a_ks = (lane >> 4);
        #pragma unroll
        for (int k16 = 0; k16 < 4; k16++) {
            uint32_t off = SWZ((uint32_t)(a_r*128 + (a_ks + k16*2)*16));
            ldsm4(qh[k16][0], qh[k16][1], qh[k16][2], qh[k16][3], smb + off);
        }
    }
    __syncthreads();   // all warps done reading Q before stage0 is overwritten

    const __half* Kh = g_kh + bhoff;
    const __half* Vh = g_vh + bhoff;

    auto prefetch_tile = [&](int kt) {
        uint32_t stg = smb + (uint32_t)(kt % 3) * 16384u;
        #pragma unroll
        for (int t = 0; t < 4; t++) {
            int idx = tid + t*256;            // 0..1023 uint4 slots
            int a   = idx >> 9;               // 0=Kh 1=Vh
            int e   = idx & 511;
            int r   = e >> 3, c16 = e & 7;
            const __half* src = ((a == 0) ? Kh : Vh) + (size_t)(kt*64 + r)*HDD + c16*8;
            cpasync16(stg + (uint32_t)a*8192u + SWZ((uint32_t)(r*128 + c16*16)), src);
        }
        CP_COMMIT();
    };

    float m0 = -1e30f, m1 = -1e30f, l0 = 0.f, l1 = 0.f;
    float O[8][4];
    #pragma unroll
    for (int n = 0; n < 8; n++)
        #pragma unroll
        for (int q = 0; q < 4; q++) O[n][q] = 0.f;

    int kb_row = ((lane >> 4) & 1)*8 + (lane & 7);
    int kb_k   = ((lane >> 3) & 1);
    int v_row  = ((lane >> 3) & 1)*8 + (lane & 7);
    int v_col  = ((lane >> 4) & 1)*8;

    prefetch_tile(0);
    prefetch_tile(1);

    const int NT = SS/64;   // 32
    for (int kt = 0; kt < NT; kt++) {
        if (kt + 1 < NT) { CP_WAIT(1); } else { CP_WAIT(0); }
        __syncthreads();

        uint32_t st = smb + (uint32_t)(kt % 3) * 16384u;

        // ---- S = qh * kh ----
        float s[8][4];
        #pragma unroll
        for (int n = 0; n < 8; n++)
            #pragma unroll
            for (int q = 0; q < 4; q++) s[n][q] = 0.f;

        #pragma unroll
        for (int k16 = 0; k16 < 4; k16++) {
            #pragma unroll
            for (int np = 0; np < 4; np++) {
                uint32_t off = SWZ((uint32_t)((np*16 + kb_row)*128 + (kb_k + k16*2)*16));
                uint32_t h0, h1, h2, h3;
                ldsm4(h0, h1, h2, h3, st + off);
                uint32_t bhi[2];
                bhi[0] = h0; bhi[1] = h1;
                mma16816(s[np*2+0], qh[k16], bhi);
                bhi[0] = h2; bhi[1] = h3;
                mma16816(s[np*2+1], qh[k16], bhi);
            }
        }

        // ---- online softmax (rows g=lane>>2 and g+8; quad shuffles) ----
        float mx0 = -1e30f, mx1 = -1e30f;
        #pragma unroll
        for (int n = 0; n < 8; n++) {
            mx0 = fmaxf(mx0, fmaxf(s[n][0], s[n][1]));
            mx1 = fmaxf(mx1, fmaxf(s[n][2], s[n][3]));
        }
        mx0 = fmaxf(mx0, __shfl_xor_sync(0xffffffffu, mx0, 1, 4));
        mx0 = fmaxf(mx0, __shfl_xor_sync(0xffffffffu, mx0, 2, 4));
        mx1 = fmaxf(mx1, __shfl_xor_sync(0xffffffffu, mx1, 1, 4));
        mx1 = fmaxf(mx1, __shfl_xor_sync(0xffffffffu, mx1, 2, 4));
        float m0n = fmaxf(m0, mx0), m1n = fmaxf(m1, mx1);
        float c0 = __expf(m0 - m0n), c1 = __expf(m1 - m1n);
        m0 = m0n; m1 = m1n;

        float rs0 = 0.f, rs1 = 0.f;
        #pragma unroll
        for (int n = 0; n < 8; n++) {
            s[n][0] = __expf(s[n][0] - m0); rs0 += s[n][0];
            s[n][1] = __expf(s[n][1] - m0); rs0 += s[n][1];
            s[n][2] = __expf(s[n][2] - m1); rs1 += s[n][2];
            s[n][3] = __expf(s[n][3] - m1); rs1 += s[n][3];
        }
        rs0 += __shfl_xor_sync(0xffffffffu, rs0, 1, 4);
        rs0 += __shfl_xor_sync(0xffffffffu, rs0, 2, 4);
        rs1 += __shfl_xor_sync(0xffffffffu, rs1, 1, 4);
        rs1 += __shfl_xor_sync(0xffffffffu, rs1, 2, 4);
        l0 = l0*c0 + rs0;
        l1 = l1*c1 + rs1;
        #pragma unroll
        for (int n = 0; n < 8; n++) {
            O[n][0] *= c0; O[n][1] *= c0; O[n][2] *= c1; O[n][3] *= c1;
        }

        // ---- O += ph * vh; P truncated to fp16 (A operand) ----
        #pragma unroll
        for (int k16 = 0; k16 < 4; k16++) {
            uint32_t ph[4];
            ph[0] = packh(s[2*k16][0],   s[2*k16][1]);
            ph[1] = packh(s[2*k16][2],   s[2*k16][3]);
            ph[2] = packh(s[2*k16+1][0], s[2*k16+1][1]);
            ph[3] = packh(s[2*k16+1][2], s[2*k16+1][3]);

            #pragma unroll
            for (int np = 0; np < 4; np++) {
                uint32_t off = SWZ((uint32_t)((k16*16 + v_row)*128 + (np*16 + v_col)*2));
                uint32_t h0, h1, h2, h3;
                ldsm4t(h0, h1, h2, h3, st + 8192u + off);
                uint32_t vhi[2];
                vhi[0] = h0; vhi[1] = h1;
                mma16816(O[np*2+0], ph, vhi);
                vhi[0] = h2; vhi[1] = h3;
                mma16816(O[np*2+1], ph, vhi);
            }
        }
        if (kt + 2 < NT) prefetch_tile(kt + 2);
    }

    // ---- epilogue: O/l -> g_at (fp16), [B,S,H] with head offset ----
    int b = bh >> 4, h = bh & 15;
    float inv0 = 1.0f / l0, inv1 = 1.0f / l1;
    int gi0 = b*SS + qt*128 + w*16 + (lane >> 2);
    int col = h*64 + (lane & 3)*2;
    #pragma unroll
    for (int n = 0; n < 8; n++) {
        #pragma unroll
        for (int half = 0; half < 2; half++) {
            int gi = gi0 + half*8;
            float v0 = O[n][half*2+0] * (half ? inv1 : inv0);
            float v1 = O[n][half*2+1] * (half ? inv1 : inv0);
            size_t idx = (size_t)gi*HH + col + n*8;
            *(__half2*)&g_at[idx] = __floats2half2_rn(v0, v1);
        }
    }
}

// ---------------------------------------------------------------------------
extern "C" void kernel_launch(void* const* d_in, const int* in_sizes, int n_in,
                              void* d_out, int out_size) {
    const float* x     = (const float*)d_in[0];
    const float* Wq    = (const float*)d_in[1];
    const float* Wk    = (const float*)d_in[2];
    const float* Wv    = (const float*)d_in[3];
    const float* Wo    = (const float*)d_in[4];
    const float* bo    = (const float*)d_in[5];
    const float* gamma = (const float*)d_in[6];
    const float* beta  = (const float*)d_in[7];
    float* out = (float*)d_out;

    ln_kernel<<<RR, 256>>>(x, gamma, beta);
    convw_kernel<<<(4*HH*HH)/256, 256>>>(Wq, Wk, Wv, Wo);

    const int GSMEM = 3*16384;   // three 16 KB stages
    cudaFuncSetAttribute(gemm_mma<0>, cudaFuncAttributeMaxDynamicSharedMemorySize, GSMEM);
    cudaFuncSetAttribute(gemm_mma<3>, cudaFuncAttributeMaxDynamicSharedMemorySize, GSMEM);

    gemm_mma<0><<<dim3(HH/128, RR/128, 3), 256, GSMEM>>>(nullptr, nullptr, nullptr);

    const int ASMEM = 3*16384;
    cudaFuncSetAttribute(attn_mma, cudaFuncAttributeMaxDynamicSharedMemorySize, ASMEM);
    attn_mma<<<dim3(SS/128, BB*NHH), 256, ASMEM>>>();

    gemm_mma<3><<<dim3(HH/128, RR/128, 1), 256, GSMEM>>>(bo, x, out);
}

// round 17
// speedup vs baseline: 8.7804x; 1.0219x over previous
#include <cuda_runtime.h>
#include <cuda_fp16.h>
#include <cstdint>
#include <math.h>

#define HH   1024
#define NHH  16
#define HDD  64
#define BB   2
#define SS   2048
#define RR   (BB*SS)   // 4096 rows

// ---------------- device scratch (no allocations allowed) -------------------
__device__ __half g_qh[RR*HH];     // [B*NH, S, HD] fp16, pre-scaled 0.125*log2e
__device__ __half g_kh[RR*HH];
__device__ __half g_vh[RR*HH];
__device__ __half g_xn[RR*HH];     // LN out fp16
__device__ __half g_wh[4*HH*HH];   // Wq,Wk,Wv,Wo fp16
__device__ __half g_at[RR*HH];     // attention out fp16

// ---------------- helpers ---------------------------------------------------
__device__ __forceinline__ uint32_t smem_u32(const void* p) {
    uint32_t a;
    asm("{ .reg .u64 t; cvta.to.shared.u64 t, %1; cvt.u32.u64 %0, t; }" : "=r"(a) : "l"(p));
    return a;
}
#define SWZ(o)   ((o) ^ (((o) >> 3) & 0x70))   // 128B-row swizzle

__device__ __forceinline__ void cpasync16(uint32_t dst, const void* src) {
    asm volatile("cp.async.cg.shared.global [%0], [%1], 16;" :: "r"(dst), "l"(src));
}
#define CP_COMMIT() asm volatile("cp.async.commit_group;" ::: "memory")
#define CP_WAIT(n)  asm volatile("cp.async.wait_group %0;" :: "n"(n) : "memory")

__device__ __forceinline__ void ldsm4(uint32_t& r0, uint32_t& r1, uint32_t& r2, uint32_t& r3,
                                      uint32_t a) {
    asm volatile("ldmatrix.sync.aligned.m8n8.x4.shared.b16 {%0,%1,%2,%3}, [%4];"
                 : "=r"(r0), "=r"(r1), "=r"(r2), "=r"(r3) : "r"(a));
}
__device__ __forceinline__ void ldsm4t(uint32_t& r0, uint32_t& r1, uint32_t& r2, uint32_t& r3,
                                       uint32_t a) {
    asm volatile("ldmatrix.sync.aligned.m8n8.x4.trans.shared.b16 {%0,%1,%2,%3}, [%4];"
                 : "=r"(r0), "=r"(r1), "=r"(r2), "=r"(r3) : "r"(a));
}
__device__ __forceinline__ void mma16816(float* c, const uint32_t* a, const uint32_t* b) {
    asm volatile("mma.sync.aligned.m16n8k16.row.col.f32.f16.f16.f32 "
                 "{%0,%1,%2,%3}, {%4,%5,%6,%7}, {%8,%9}, {%0,%1,%2,%3};"
                 : "+f"(c[0]), "+f"(c[1]), "+f"(c[2]), "+f"(c[3])
                 : "r"(a[0]), "r"(a[1]), "r"(a[2]), "r"(a[3]), "r"(b[0]), "r"(b[1]));
}
__device__ __forceinline__ uint32_t packh(float p0, float p1) {   // p0 -> low half
    __half2 h = __floats2half2_rn(p0, p1);
    return *reinterpret_cast<uint32_t*>(&h);
}

// ---------------------------------------------------------------------------
// LayerNorm: one block per row, 256 threads, float4 per thread; emits fp16.
// ---------------------------------------------------------------------------
__global__ void ln_kernel(const float* __restrict__ x,
                          const float* __restrict__ gamma,
                          const float* __restrict__ beta) {
    int row = blockIdx.x;
    int t   = threadIdx.x;
    const float4* xr = (const float4*)(x + (size_t)row*HH);
    float4 v = xr[t];
    float s  = v.x + v.y + v.z + v.w;
    float sq = v.x*v.x + v.y*v.y + v.z*v.z + v.w*v.w;

    __shared__ float ssum[8], ssq[8];
    #pragma unroll
    for (int o = 16; o >= 1; o >>= 1) {
        s  += __shfl_xor_sync(0xffffffffu, s,  o);
        sq += __shfl_xor_sync(0xffffffffu, sq, o);
    }
    int warp = t >> 5, lane = t & 31;
    if (lane == 0) { ssum[warp] = s; ssq[warp] = sq; }
    __syncthreads();
    s = 0.f; sq = 0.f;
    #pragma unroll
    for (int i = 0; i < 8; i++) { s += ssum[i]; sq += ssq[i]; }

    float mu  = s * (1.0f/HH);
    float var = sq * (1.0f/HH) - mu*mu;
    float inv = rsqrtf(var + 1e-5f);

    float4 g  = ((const float4*)gamma)[t];
    float4 bt = ((const float4*)beta)[t];
    size_t base = (size_t)row*HH + t*4;
    g_xn[base+0] = __float2half((v.x-mu)*inv*g.x + bt.x);
    g_xn[base+1] = __float2half((v.y-mu)*inv*g.y + bt.y);
    g_xn[base+2] = __float2half((v.z-mu)*inv*g.z + bt.z);
    g_xn[base+3] = __float2half((v.w-mu)*inv*g.w + bt.w);
}

// ---------------------------------------------------------------------------
// Weight conversion fp32 -> fp16, all 4 W at once.
// ---------------------------------------------------------------------------
__global__ void convw_kernel(const float* __restrict__ Wq, const float* __restrict__ Wk,
                             const float* __restrict__ Wv, const float* __restrict__ Wo) {
    int i = blockIdx.x*blockDim.x + threadIdx.x;
    const int M = HH*HH;
    const float* src = (i < M) ? Wq : (i < 2*M) ? Wk : (i < 3*M) ? Wv : Wo;
    g_wh[i] = __float2half(src[i & (M-1)]);
}

// ---------------------------------------------------------------------------
// fp16 HMMA NT-GEMM: C = A * W^T. 3-stage cp.async ring, K-chunk 64.
// Stage = A(16K)|W(16K) = 32KB; 3 stages = 96KB; 2 CTAs/SM. 16 chunks.
// 8 warps (2m x 4n of 64x32).
// MODE 0: dst = q/k/v fp16 head-layout (q pre-scaled by 0.125*log2e).
// MODE 3: out + bias + residual (fp32).
// ---------------------------------------------------------------------------
template<int MODE>
__global__ __launch_bounds__(256, 2) void gemm_mma(const float* __restrict__ bo,
                                                   const float* __restrict__ resid,
                                                   float* __restrict__ out) {
    extern __shared__ char sm[];
    uint32_t smb = smem_u32(sm);

    int tid = threadIdx.x;
    int w = tid >> 5, lane = tid & 31;
    int wm = w & 1, wn = w >> 1;
    int row0 = blockIdx.y * 128;
    int col0 = blockIdx.x * 128;
    int widx = (MODE == 3) ? 3 : blockIdx.z;

    const __half* A  = (MODE == 3) ? g_at : g_xn;
    const __half* Wh = g_wh + (size_t)widx*HH*HH;

    float acc[4][4][4];
    #pragma unroll
    for (int i = 0; i < 4; i++)
        #pragma unroll
        for (int j = 0; j < 4; j++)
            #pragma unroll
            for (int q = 0; q < 4; q++) acc[i][j][q] = 0.f;

    auto prefetch_chunk = [&](int chunk) {
        int kt = chunk * 64;
        uint32_t stg = smb + (uint32_t)(chunk % 3) * 32768u;
        #pragma unroll
        for (int t = 0; t < 8; t++) {
            int idx = tid + t*256;                // 0..2047 16B slots
            int a   = idx >> 10;                  // 0=A 1=W
            int e   = idx & 1023;
            int r   = e >> 3, c16 = e & 7;        // 128 rows x 8 segs of 8 halves
            const __half* src =
                (a == 0) ? A  + (size_t)(row0 + r)*HH + kt :
                           Wh + (size_t)(col0 + r)*HH + kt;
            cpasync16(stg + (uint32_t)a*16384u + SWZ((uint32_t)(r*128 + c16*16)),
                      src + c16*8);
        }
        CP_COMMIT();
    };

    prefetch_chunk(0);
    prefetch_chunk(1);

    int a_r  = wm*64 + ((lane >> 3) & 1)*8 + (lane & 7);
    int a_ks = (lane >> 4);
    int b_r  = wn*32 + ((lane >> 4) & 1)*8 + (lane & 7);
    int b_ks = ((lane >> 3) & 1);

    for (int chunk = 0; chunk < 16; ++chunk) {
        if (chunk + 1 < 16) { CP_WAIT(1); } else { CP_WAIT(0); }
        __syncthreads();

        uint32_t st = smb + (uint32_t)(chunk % 3) * 32768u;

        #pragma unroll
        for (int k16 = 0; k16 < 4; ++k16) {
            int ksA = (a_ks + k16*2) * 16;
            int ksB = (b_ks + k16*2) * 16;

            uint32_t Af[4][4], Bf[4][2];
            #pragma unroll
            for (int mf = 0; mf < 4; mf++) {
                uint32_t off = SWZ((uint32_t)((a_r + mf*16)*128 + ksA));
                ldsm4(Af[mf][0], Af[mf][1], Af[mf][2], Af[mf][3], st + off);
            }
            #pragma unroll
            for (int nh = 0; nh < 2; nh++) {
                uint32_t off = SWZ((uint32_t)((b_r + nh*16)*128 + ksB));
                uint32_t r0, r1, r2, r3;
                ldsm4(r0, r1, r2, r3, st + 16384u + off);
                Bf[nh*2+0][0] = r0; Bf[nh*2+0][1] = r1;
                Bf[nh*2+1][0] = r2; Bf[nh*2+1][1] = r3;
            }
            #pragma unroll
            for (int mf = 0; mf < 4; mf++)
                #pragma unroll
                for (int nf = 0; nf < 4; nf++)
                    mma16816(acc[mf][nf], Af[mf], Bf[nf]);
        }
        if (chunk + 2 < 16) prefetch_chunk(chunk + 2);
    }

    // Q pre-scale folds attention 1/sqrt(64) AND log2(e) for base-2 softmax.
    float qscale = (MODE < 3 && blockIdx.z == 0) ? 0.125f * 1.44269504f : 1.0f;
    #pragma unroll
    for (int mf = 0; mf < 4; mf++) {
        int mr = row0 + wm*64 + mf*16 + (lane >> 2);
        #pragma unroll
        for (int nf = 0; nf < 4; nf++) {
            int nc = col0 + wn*32 + nf*8 + (lane & 3)*2;
            #pragma unroll
            for (int half = 0; half < 2; half++) {
                int gi = mr + half*8;
                float v0 = acc[mf][nf][half*2 + 0];
                float v1 = acc[mf][nf][half*2 + 1];
                if (MODE < 3) {
                    v0 *= qscale; v1 *= qscale;
                    int b  = gi >> 11;
                    int s_ = gi & 2047;
                    int h  = nc >> 6;
                    int d  = nc & 63;
                    __half* dh = (blockIdx.z == 0) ? g_qh : (blockIdx.z == 1) ? g_kh : g_vh;
                    size_t base = (size_t)(((b << 4) + h)*SS + s_)*HDD + d;
                    *(__half2*)&dh[base] = __floats2half2_rn(v0, v1);
                } else {
                    size_t base = (size_t)gi*HH + nc;
                    const float2 rr = *(const float2*)&resid[base];
                    float2* p = (float2*)&out[base];
                    *p = make_float2(v0 + bo[nc] + rr.x, v1 + bo[nc+1] + rr.y);
                }
            }
        }
    }
}

// ---------------------------------------------------------------------------
// fp16 HMMA flash attention, base-2 softmax: S2 = qh*kh (log2e folded into q),
// P = exp2(S2 - m2), O = ph*vh. 3-stage cp.async ring, one barrier per K-tile.
// Block = (bh, 128 queries), 8 warps x 16 q-rows; 64-key tiles.
// Stage (16KB) = Kh|Vh, 8KB apiece. Q staged into stage0 first.
// ---------------------------------------------------------------------------
__global__ __launch_bounds__(256, 2) void attn_mma() {
    extern __shared__ char sm[];
    uint32_t smb = smem_u32(sm);

    int tid = threadIdx.x;
    int w = tid >> 5, lane = tid & 31;
    int bh = blockIdx.y;
    int qt = blockIdx.x;              // 0..15 (128-query tiles)
    size_t bhoff = (size_t)bh*SS*HDD;

    // ---- stage Q tile (128x64) into stage0, then preload A-fragments ----
    {
        const __half* Qh = g_qh + bhoff + (size_t)qt*128*HDD;
        #pragma unroll
        for (int t = 0; t < 4; t++) {
            int idx = tid + t*256;            // 0..1023 uint4 slots
            int r   = idx >> 3, c16 = idx & 7;
            cpasync16(smb + SWZ((uint32_t)(r*128 + c16*16)), Qh + (size_t)r*HDD + c16*8);
        }
        CP_COMMIT();
        CP_WAIT(0);
    }
    __syncthreads();

    uint32_t qh[4][4];
    {
        int a_r  = w*16 + ((lane >> 3) & 1)*8 + (lane & 7);
        int a_ks = (lane >> 4);
        #pragma unroll
        for (int k16 = 0; k16 < 4; k16++) {
            uint32_t off = SWZ((uint32_t)(a_r*128 + (a_ks + k16*2)*16));
            ldsm4(qh[k16][0], qh[k16][1], qh[k16][2], qh[k16][3], smb + off);
        }
    }
    __syncthreads();   // all warps done reading Q before stage0 is overwritten

    const __half* Kh = g_kh + bhoff;
    const __half* Vh = g_vh + bhoff;

    auto prefetch_tile = [&](int kt) {
        uint32_t stg = smb + (uint32_t)(kt % 3) * 16384u;
        #pragma unroll
        for (int t = 0; t < 4; t++) {
            int idx = tid + t*256;            // 0..1023 uint4 slots
            int a   = idx >> 9;               // 0=Kh 1=Vh
            int e   = idx & 511;
            int r   = e >> 3, c16 = e & 7;
            const __half* src = ((a == 0) ? Kh : Vh) + (size_t)(kt*64 + r)*HDD + c16*8;
            cpasync16(stg + (uint32_t)a*8192u + SWZ((uint32_t)(r*128 + c16*16)), src);
        }
        CP_COMMIT();
    };

    float m0 = -1e30f, m1 = -1e30f, l0 = 0.f, l1 = 0.f;
    float O[8][4];
    #pragma unroll
    for (int n = 0; n < 8; n++)
        #pragma unroll
        for (int q = 0; q < 4; q++) O[n][q] = 0.f;

    int kb_row = ((lane >> 4) & 1)*8 + (lane & 7);
    int kb_k   = ((lane >> 3) & 1);
    int v_row  = ((lane >> 3) & 1)*8 + (lane & 7);
    int v_col  = ((lane >> 4) & 1)*8;

    prefetch_tile(0);
    prefetch_tile(1);

    const int NT = SS/64;   // 32
    for (int kt = 0; kt < NT; kt++) {
        if (kt + 1 < NT) { CP_WAIT(1); } else { CP_WAIT(0); }
        __syncthreads();

        uint32_t st = smb + (uint32_t)(kt % 3) * 16384u;

        // ---- S2 = qh * kh (already in log2 domain) ----
        float s[8][4];
        #pragma unroll
        for (int n = 0; n < 8; n++)
            #pragma unroll
            for (int q = 0; q < 4; q++) s[n][q] = 0.f;

        #pragma unroll
        for (int k16 = 0; k16 < 4; k16++) {
            #pragma unroll
            for (int np = 0; np < 4; np++) {
                uint32_t off = SWZ((uint32_t)((np*16 + kb_row)*128 + (kb_k + k16*2)*16));
                uint32_t h0, h1, h2, h3;
                ldsm4(h0, h1, h2, h3, st + off);
                uint32_t bhi[2];
                bhi[0] = h0; bhi[1] = h1;
                mma16816(s[np*2+0], qh[k16], bhi);
                bhi[0] = h2; bhi[1] = h3;
                mma16816(s[np*2+1], qh[k16], bhi);
            }
        }

        // ---- online softmax in base-2 (rows g=lane>>2 and g+8; quad shuffles) ----
        float mx0 = -1e30f, mx1 = -1e30f;
        #pragma unroll
        for (int n = 0; n < 8; n++) {
            mx0 = fmaxf(mx0, fmaxf(s[n][0], s[n][1]));
            mx1 = fmaxf(mx1, fmaxf(s[n][2], s[n][3]));
        }
        mx0 = fmaxf(mx0, __shfl_xor_sync(0xffffffffu, mx0, 1, 4));
        mx0 = fmaxf(mx0, __shfl_xor_sync(0xffffffffu, mx0, 2, 4));
        mx1 = fmaxf(mx1, __shfl_xor_sync(0xffffffffu, mx1, 1, 4));
        mx1 = fmaxf(mx1, __shfl_xor_sync(0xffffffffu, mx1, 2, 4));
        float m0n = fmaxf(m0, mx0), m1n = fmaxf(m1, mx1);
        float c0 = exp2f(m0 - m0n), c1 = exp2f(m1 - m1n);
        m0 = m0n; m1 = m1n;

        float rs0 = 0.f, rs1 = 0.f;
        #pragma unroll
        for (int n = 0; n < 8; n++) {
            s[n][0] = exp2f(s[n][0] - m0); rs0 += s[n][0];
            s[n][1] = exp2f(s[n][1] - m0); rs0 += s[n][1];
            s[n][2] = exp2f(s[n][2] - m1); rs1 += s[n][2];
            s[n][3] = exp2f(s[n][3] - m1); rs1 += s[n][3];
        }
        rs0 += __shfl_xor_sync(0xffffffffu, rs0, 1, 4);
        rs0 += __shfl_xor_sync(0xffffffffu, rs0, 2, 4);
        rs1 += __shfl_xor_sync(0xffffffffu, rs1, 1, 4);
        rs1 += __shfl_xor_sync(0xffffffffu, rs1, 2, 4);
        l0 = l0*c0 + rs0;
        l1 = l1*c1 + rs1;
        #pragma unroll
        for (int n = 0; n < 8; n++) {
            O[n][0] *= c0; O[n][1] *= c0; O[n][2] *= c1; O[n][3] *= c1;
        }

        // ---- O += ph * vh; P truncated to fp16 (A operand) ----
        #pragma unroll
        for (int k16 = 0; k16 < 4; k16++) {
            uint32_t ph[4];
            ph[0] = packh(s[2*k16][0],   s[2*k16][1]);
            ph[1] = packh(s[2*k16][2],   s[2*k16][3]);
            ph[2] = packh(s[2*k16+1][0], s[2*k16+1][1]);
            ph[3] = packh(s[2*k16+1][2], s[2*k16+1][3]);

            #pragma unroll
            for (int np = 0; np < 4; np++) {
                uint32_t off = SWZ((uint32_t)((k16*16 + v_row)*128 + (np*16 + v_col)*2));
                uint32_t h0, h1, h2, h3;
                ldsm4t(h0, h1, h2, h3, st + 8192u + off);
                uint32_t vhi[2];
                vhi[0] = h0; vhi[1] = h1;
                mma16816(O[np*2+0], ph, vhi);
                vhi[0] = h2; vhi[1] = h3;
                mma16816(O[np*2+1], ph, vhi);
            }
        }
        if (kt + 2 < NT) prefetch_tile(kt + 2);
    }

    // ---- epilogue: O/l -> g_at (fp16), [B,S,H] with head offset ----
    int b = bh >> 4, h = bh & 15;
    float inv0 = 1.0f / l0, inv1 = 1.0f / l1;
    int gi0 = b*SS + qt*128 + w*16 + (lane >> 2);
    int col = h*64 + (lane & 3)*2;
    #pragma unroll
    for (int n = 0; n < 8; n++) {
        #pragma unroll
        for (int half = 0; half < 2; half++) {
            int gi = gi0 + half*8;
            float v0 = O[n][half*2+0] * (half ? inv1 : inv0);
            float v1 = O[n][half*2+1] * (half ? inv1 : inv0);
            size_t idx = (size_t)gi*HH + col + n*8;
            *(__half2*)&g_at[idx] = __floats2half2_rn(v0, v1);
        }
    }
}

// ---------------------------------------------------------------------------
extern "C" void kernel_launch(void* const* d_in, const int* in_sizes, int n_in,
                              void* d_out, int out_size) {
    const float* x     = (const float*)d_in[0];
    const float* Wq    = (const float*)d_in[1];
    const float* Wk    = (const float*)d_in[2];
    const float* Wv    = (const float*)d_in[3];
    const float* Wo    = (const float*)d_in[4];
    const float* bo    = (const float*)d_in[5];
    const float* gamma = (const float*)d_in[6];
    const float* beta  = (const float*)d_in[7];
    float* out = (float*)d_out;

    ln_kernel<<<RR, 256>>>(x, gamma, beta);
    convw_kernel<<<(4*HH*HH)/256, 256>>>(Wq, Wk, Wv, Wo);

    const int GSMEM = 3*32768;   // three 32 KB stages
    cudaFuncSetAttribute(gemm_mma<0>, cudaFuncAttributeMaxDynamicSharedMemorySize, GSMEM);
    cudaFuncSetAttribute(gemm_mma<3>, cudaFuncAttributeMaxDynamicSharedMemorySize, GSMEM);

    gemm_mma<0><<<dim3(HH/128, RR/128, 3), 256, GSMEM>>>(nullptr, nullptr, nullptr);

    const int ASMEM = 3*16384;
    cudaFuncSetAttribute(attn_mma, cudaFuncAttributeMaxDynamicSharedMemorySize, ASMEM);
    attn_mma<<<dim3(SS/128, BB*NHH), 256, ASMEM>>>();

    gemm_mma<3><<<dim3(HH/128, RR/128, 1), 256, GSMEM>>>(bo, x, out);
}